// round 6
// baseline (speedup 1.0000x reference)
#include <cuda_runtime.h>
#include <cuda_bf16.h>
#include <math.h>
#include <stdint.h>

#define BATCH   2
#define LSEQ    2048
#define CDIM    384
#define DI      768
#define DS      16
#define DTR     24
#define MR      (BATCH*LSEQ)     /* 4096 rows */
#define NC      32               /* scan chunks */
#define CH      (LSEQ/NC)        /* 64 steps per chunk */
#define DBC_S   64               /* padded stride for dbc rows (56 used) */
#define XSPL    8                /* x_proj K-split */

// ---------------- scratch (static device globals; no allocation) ----------
__device__ float g_xt   [MR*CDIM];       // transposed input (B,L,C)
__device__ float g_xn   [MR*CDIM];       // layernorm1 output (B,L,C)
__device__ float g_xz   [MR*2*DI];       // in_proj output (u | z)
__device__ float g_u    [MR*DI];         // conv+silu output
__device__ float g_dbcp [XSPL*MR*DBC_S]; // x_proj K-split partials
__device__ float g_dbc  [MR*DBC_S];      // x_proj output (dt|B|C), padded
__device__ float g_delta[MR*DI];         // softplus(dt_proj)
__device__ float g_y    [MR*DI];         // scan output after epilogue
__device__ float g_mo   [2*MR*CDIM];     // out_proj K-split partials
__device__ float g_res  [MR*CDIM];       // ln2 output (B,L,C) pre-transpose
__device__ float g_hend [BATCH*NC*DI*DS];
__device__ float g_pend [BATCH*NC*DI*DS];
__device__ float g_hin  [BATCH*NC*DI*DS];
// bf16x3 split operands
__device__ __nv_bfloat16 g_a1[MR*3*CDIM];       // in_proj A'  [4096,1152]
__device__ __nv_bfloat16 g_w1[2*DI*3*CDIM];     // in_proj W'  [1536,1152]
__device__ __nv_bfloat16 g_a2[MR*3*DI];         // out_proj A' [4096,2304]
__device__ __nv_bfloat16 g_w2[CDIM*3*DI];       // out_proj W' [384,2304]

// ---------------- helpers ---------------------------------------------------
__device__ __forceinline__ uint32_t smem_u32(const void* p) {
    uint32_t a;
    asm("{ .reg .u64 t; cvta.to.shared.u64 t, %1; cvt.u32.u64 %0, t; }"
        : "=r"(a) : "l"(p));
    return a;
}
#define LDSM4(r0, r1, r2, r3, a) \
    asm volatile("ldmatrix.sync.aligned.m8n8.x4.shared.b16 {%0,%1,%2,%3}, [%4];" \
                 : "=r"(r0), "=r"(r1), "=r"(r2), "=r"(r3) : "r"(a))
#define MMA16816(c, a, b) \
    asm volatile("mma.sync.aligned.m16n8k16.row.col.f32.bf16.bf16.f32 " \
                 "{%0,%1,%2,%3}, {%4,%5,%6,%7}, {%8,%9}, {%0,%1,%2,%3};" \
                 : "+f"((c)[0]), "+f"((c)[1]), "+f"((c)[2]), "+f"((c)[3]) \
                 : "r"((a)[0]), "r"((a)[1]), "r"((a)[2]), "r"((a)[3]), \
                   "r"((b)[0]), "r"((b)[1]))

// ---------------- bf16x3 split conversion ---------------------------------
// A-mode: dst row = [hi | lo | hi]; W-mode: dst row = [hi | hi | lo]
__global__ void k_cvt(const float* __restrict__ src, __nv_bfloat16* __restrict__ dst,
                      int K, int wmode) {
    size_t i = (size_t)blockIdx.x * 256 + threadIdx.x;
    int r = (int)(i / K), k = (int)(i % K);
    float a = src[i];
    __nv_bfloat16 hi = __float2bfloat16(a);
    __nv_bfloat16 lo = __float2bfloat16(a - __bfloat162float(hi));
    size_t base = (size_t)r * 3 * K;
    dst[base + k] = hi;
    if (wmode) { dst[base + K + k] = hi; dst[base + 2*K + k] = lo; }
    else       { dst[base + K + k] = lo; dst[base + 2*K + k] = hi; }
}

// ---------------- bf16 mma.sync GEMM: C[M,N] (+z split) --------------------
// C[z][M,N] = A[M, z*Kl:(z+1)*Kl] * W[N, same]^T ; row stride = lda (= total K3)
// 128x128 block, 8 warps (4x2), warp tile 32x64, K-chunk 32, double buffer.
#define KCH   32
#define SROW  40            /* padded SMEM row, bf16 elems */
#define SSTG  (128*SROW)    /* elems per stage */
__global__ void __launch_bounds__(256)
k_bgemm(const __nv_bfloat16* __restrict__ A, const __nv_bfloat16* __restrict__ W,
        float* __restrict__ C, int N, int Kl, int lda, int cstride) {
    __shared__ __align__(16) __nv_bfloat16 As[2*SSTG];
    __shared__ __align__(16) __nv_bfloat16 Ws[2*SSTG];

    int tid = threadIdx.x, lane = tid & 31, wid = tid >> 5;
    int warp_m = wid & 3, warp_n = wid >> 2;          // 4 x 2 warps
    int m0 = blockIdx.y * 128, n0 = blockIdx.x * 128;
    int z = blockIdx.z;
    A += (size_t)z * Kl;
    W += (size_t)z * Kl;
    C += (size_t)z * cstride;

    // global load mapping: row = tid>>1, col0 = (tid&1)*16  (16 bf16 each)
    int lrow = tid >> 1, lcol = (tid & 1) * 16;
    const __nv_bfloat16* Ag = A + (size_t)(m0 + lrow) * lda + lcol;
    const __nv_bfloat16* Wg = W + (size_t)(n0 + lrow) * lda + lcol;

    // ldmatrix base addresses (bytes)
    uint32_t aBase = smem_u32(As)
        + (uint32_t)((warp_m*32 + (lane & 15)) * SROW + ((lane >> 4) & 1) * 8) * 2;
    uint32_t bBase = smem_u32(Ws)
        + (uint32_t)((warp_n*64 + (lane & 7) + ((lane >> 4) & 1) * 8) * SROW
                     + ((lane >> 3) & 1) * 8) * 2;

    float acc[2][8][4];
#pragma unroll
    for (int i = 0; i < 2; i++)
#pragma unroll
        for (int j = 0; j < 8; j++)
#pragma unroll
            for (int q = 0; q < 4; q++) acc[i][j][q] = 0.f;

    // preload chunk 0 into stage 0
    {
        uint4 a0 = *(const uint4*)(Ag);
        uint4 a1 = *(const uint4*)(Ag + 8);
        uint4 w0 = *(const uint4*)(Wg);
        uint4 w1 = *(const uint4*)(Wg + 8);
        *(uint4*)&As[lrow*SROW + lcol]     = a0;
        *(uint4*)&As[lrow*SROW + lcol + 8] = a1;
        *(uint4*)&Ws[lrow*SROW + lcol]     = w0;
        *(uint4*)&Ws[lrow*SROW + lcol + 8] = w1;
    }
    __syncthreads();

    int NKC = Kl / KCH;
    for (int kc = 0; kc < NKC; kc++) {
        int s = kc & 1;
        uint32_t aS = aBase + (uint32_t)s * SSTG * 2;
        uint32_t bS = bBase + (uint32_t)s * SSTG * 2;
        bool hasNext = (kc + 1 < NKC);
        uint4 na0, na1, nw0, nw1;
        if (hasNext) {
            const __nv_bfloat16* ap = Ag + (size_t)(kc + 1) * KCH;
            const __nv_bfloat16* wp = Wg + (size_t)(kc + 1) * KCH;
            na0 = *(const uint4*)(ap);
            na1 = *(const uint4*)(ap + 8);
            nw0 = *(const uint4*)(wp);
            nw1 = *(const uint4*)(wp + 8);
        }
#pragma unroll
        for (int ks = 0; ks < 2; ks++) {
            uint32_t af[2][4];
#pragma unroll
            for (int mi = 0; mi < 2; mi++)
                LDSM4(af[mi][0], af[mi][1], af[mi][2], af[mi][3],
                      aS + (uint32_t)(mi*16*SROW + ks*16) * 2);
            uint32_t bf[8][2];
#pragma unroll
            for (int p = 0; p < 4; p++) {
                uint32_t r0, r1, r2, r3;
                LDSM4(r0, r1, r2, r3, bS + (uint32_t)(p*16*SROW + ks*16) * 2);
                bf[2*p][0] = r0;   bf[2*p][1] = r1;
                bf[2*p+1][0] = r2; bf[2*p+1][1] = r3;
            }
#pragma unroll
            for (int mi = 0; mi < 2; mi++)
#pragma unroll
                for (int nj = 0; nj < 8; nj++)
                    MMA16816(acc[mi][nj], af[mi], bf[nj]);
        }
        if (hasNext) {
            int d = (s ^ 1) * SSTG;
            *(uint4*)&As[d + lrow*SROW + lcol]     = na0;
            *(uint4*)&As[d + lrow*SROW + lcol + 8] = na1;
            *(uint4*)&Ws[d + lrow*SROW + lcol]     = nw0;
            *(uint4*)&Ws[d + lrow*SROW + lcol + 8] = nw1;
        }
        __syncthreads();
    }

    // epilogue: acc[mi][nj]: rows warp_m*32+mi*16+lane/4 (+8), cols warp_n*64+nj*8+(lane%4)*2
    int rbase = m0 + warp_m*32 + (lane >> 2);
    int cbase = n0 + warp_n*64 + (lane & 3)*2;
#pragma unroll
    for (int mi = 0; mi < 2; mi++) {
#pragma unroll
        for (int nj = 0; nj < 8; nj++) {
            float* cp0 = C + (size_t)(rbase + mi*16) * N + cbase + nj*8;
            float* cp1 = cp0 + 8*N;
            *(float2*)cp0 = make_float2(acc[mi][nj][0], acc[mi][nj][1]);
            *(float2*)cp1 = make_float2(acc[mi][nj][2], acc[mi][nj][3]);
        }
    }
}

// ---------------- K0: tiled transpose  in[z][R][Cc] -> out[z][Cc][R] ------
__global__ void k_tr(const float* __restrict__ in, float* __restrict__ out,
                     int R, int Cc) {
    __shared__ float t[32][33];
    const float* ip = in  + (size_t)blockIdx.z * R * Cc;
    float*       op = out + (size_t)blockIdx.z * R * Cc;
    int c0 = blockIdx.x * 32;
    int r0 = blockIdx.y * 32;
    int lx = threadIdx.x, ly = threadIdx.y;   // 32 x 8
#pragma unroll
    for (int i = 0; i < 4; i++)
        t[ly + i*8][lx] = ip[(size_t)(r0 + ly + i*8) * Cc + c0 + lx];
    __syncthreads();
#pragma unroll
    for (int i = 0; i < 4; i++)
        op[(size_t)(c0 + ly + i*8) * R + r0 + lx] = t[lx][ly + i*8];
}

// ---------------- K1: layernorm over C (row-major, coalesced) --------------
__global__ void k_ln1(const float* __restrict__ xt,
                      const float* __restrict__ w,
                      const float* __restrict__ bias) {
    int m = blockIdx.x;
    int tid = threadIdx.x;
    const float* xp = xt + (size_t)m * CDIM;
    float v[3]; float s = 0.f, s2 = 0.f;
#pragma unroll
    for (int i = 0; i < 3; i++) {
        int c = tid + i*128;
        float t = xp[c];
        v[i] = t; s += t; s2 += t*t;
    }
    __shared__ float sh1[128], sh2[128];
    sh1[tid] = s; sh2[tid] = s2; __syncthreads();
    for (int o = 64; o > 0; o >>= 1) {
        if (tid < o) { sh1[tid] += sh1[tid+o]; sh2[tid] += sh2[tid+o]; }
        __syncthreads();
    }
    float mu  = sh1[0] * (1.f/CDIM);
    float var = sh2[0] * (1.f/CDIM) - mu*mu;
    float rs  = rsqrtf(var + 1e-5f);
#pragma unroll
    for (int i = 0; i < 3; i++) {
        int c = tid + i*128;
        g_xn[(size_t)m*CDIM + c] = (v[i]-mu)*rs*w[c] + bias[c];
    }
}

// ---------------- K3: causal depthwise conv (D_CONV=4) + bias + silu ------
__global__ void k_conv(const float* __restrict__ cw, const float* __restrict__ cb) {
    int idx = blockIdx.x*256 + threadIdx.x;
    int d = idx % DI, m = idx / DI;
    int l = m % LSEQ;
    float acc = cb[d];
#pragma unroll
    for (int j = 0; j < 4; j++) {
        int ll = l - 3 + j;
        if (ll >= 0)
            acc = fmaf(cw[d*4+j], g_xz[(size_t)(m-3+j)*(2*DI) + d], acc);
    }
    float sg = 1.f / (1.f + __expf(-acc));
    g_u[idx] = acc * sg;
}

// ---------------- K4: x_proj partial  (K-split via blockIdx.y) -------------
__global__ void __launch_bounds__(256)
k_xproj(const float* __restrict__ W) {
    __shared__ float us[32][68];   // [k][m]
    __shared__ float ws[56][33];   // [n][k]
    int tid = threadIdx.x;
    int m0 = blockIdx.x * 64;
    int z  = blockIdx.y;
    int kbase = z * (DI/XSPL);     // 96
    int n  = tid & 63, mg = tid >> 6;
    int nn = (n < 56) ? n : 55;
    float acc[16];
#pragma unroll
    for (int i = 0; i < 16; i++) acc[i] = 0.f;

    for (int k0 = kbase; k0 < kbase + DI/XSPL; k0 += 32) {
        __syncthreads();
        for (int v = tid; v < 512; v += 256) {
            int mr = v >> 3, kb = v & 7;
            float4 t = *(const float4*)(g_u + (size_t)(m0+mr)*DI + k0 + kb*4);
            us[kb*4+0][mr] = t.x; us[kb*4+1][mr] = t.y;
            us[kb*4+2][mr] = t.z; us[kb*4+3][mr] = t.w;
        }
        for (int v = tid; v < 448; v += 256) {
            int nr = v >> 3, kb = v & 7;
            float4 t = *(const float4*)(W + (size_t)nr*DI + k0 + kb*4);
            ws[nr][kb*4+0] = t.x; ws[nr][kb*4+1] = t.y;
            ws[nr][kb*4+2] = t.z; ws[nr][kb*4+3] = t.w;
        }
        __syncthreads();
#pragma unroll 4
        for (int kk = 0; kk < 32; kk++) {
            float wv = ws[nn][kk];
            float4 u0 = *(const float4*)&us[kk][mg*16+0];
            float4 u1 = *(const float4*)&us[kk][mg*16+4];
            float4 u2 = *(const float4*)&us[kk][mg*16+8];
            float4 u3 = *(const float4*)&us[kk][mg*16+12];
            acc[0]  = fmaf(u0.x, wv, acc[0]);  acc[1]  = fmaf(u0.y, wv, acc[1]);
            acc[2]  = fmaf(u0.z, wv, acc[2]);  acc[3]  = fmaf(u0.w, wv, acc[3]);
            acc[4]  = fmaf(u1.x, wv, acc[4]);  acc[5]  = fmaf(u1.y, wv, acc[5]);
            acc[6]  = fmaf(u1.z, wv, acc[6]);  acc[7]  = fmaf(u1.w, wv, acc[7]);
            acc[8]  = fmaf(u2.x, wv, acc[8]);  acc[9]  = fmaf(u2.y, wv, acc[9]);
            acc[10] = fmaf(u2.z, wv, acc[10]); acc[11] = fmaf(u2.w, wv, acc[11]);
            acc[12] = fmaf(u3.x, wv, acc[12]); acc[13] = fmaf(u3.y, wv, acc[13]);
            acc[14] = fmaf(u3.z, wv, acc[14]); acc[15] = fmaf(u3.w, wv, acc[15]);
        }
    }
    if (n < 56) {
#pragma unroll
        for (int i = 0; i < 16; i++)
            g_dbcp[((size_t)z*MR + m0 + mg*16 + i)*DBC_S + n] = acc[i];
    }
}

// ---------------- K4b: reduce the K-split partials -------------------------
__global__ void k_dbcred() {
    size_t i = (size_t)blockIdx.x*256 + threadIdx.x;    // < MR*DBC_S
    float s = 0.f;
#pragma unroll
    for (int z = 0; z < XSPL; z++) s += g_dbcp[(size_t)z*MR*DBC_S + i];
    g_dbc[i] = s;
}

// ---------------- K5: dt_proj + softplus -> delta --------------------------
__global__ void k_dtproj(const float* __restrict__ W, const float* __restrict__ bias) {
    __shared__ float sdt[16][24];
    int tid = threadIdx.x;
    int m0 = blockIdx.x * 16;
    for (int idx = tid; idx < 16*24; idx += 256) {
        int mi = idx / 24, r = idx % 24;
        sdt[mi][r] = g_dbc[(size_t)(m0+mi)*DBC_S + r];
    }
    __syncthreads();
    for (int d = tid; d < DI; d += 256) {
        float wr[24];
#pragma unroll
        for (int r = 0; r < 24; r++) wr[r] = W[d*24 + r];
        float bz = bias[d];
        for (int mi = 0; mi < 16; mi++) {
            float a = bz;
#pragma unroll
            for (int r = 0; r < 24; r++) a = fmaf(sdt[mi][r], wr[r], a);
            float sp = (a > 20.f) ? a : log1pf(expf(a));
            g_delta[(size_t)(m0+mi)*DI + d] = sp;
        }
    }
}

// ---------------- scan helpers ---------------------------------------------
__device__ __forceinline__ void scan_dA(bool fast, float a1, float delta,
                                        const float* __restrict__ Alog, int d,
                                        float dA[DS]) {
    if (fast) {
        float p = __expf(delta * a1);      // dA[s] = p^(s+1)
        dA[0] = p;
#pragma unroll
        for (int s = 1; s < DS; s++) dA[s] = dA[s-1] * p;
    } else {
#pragma unroll
        for (int s = 0; s < DS; s++)
            dA[s] = __expf(delta * (-__expf(Alog[d*DS + s])));
    }
}

__device__ __forceinline__ bool fast_check(const float* __restrict__ Alog,
                                           int d, float& a1) {
    a1 = -__expf(Alog[d*DS + 0]);
    bool fast = true;
#pragma unroll
    for (int s = 0; s < DS; s++) {
        float as = -__expf(Alog[d*DS + s]);
        fast = fast && (fabsf(as - (float)(s+1)*a1) <= 1e-4f*fabsf(as) + 1e-12f);
    }
    return fast;
}

// ---------------- K6a: chunk-local scan (carry + product) ------------------
__global__ void __launch_bounds__(256)
k_scan1(const float* __restrict__ Alog) {
    int g = blockIdx.x*256 + threadIdx.x;     // B*NC*DI threads
    int d = g % DI; int rest = g / DI;
    int chunk = rest % NC; int b = rest / NC;

    float a1; bool fast = fast_check(Alog, d, a1);
    float h[DS], P[DS];
#pragma unroll
    for (int s = 0; s < DS; s++) { h[s] = 0.f; P[s] = 1.f; }

    int mbase = b*LSEQ + chunk*CH;
    for (int t = 0; t < CH; t++) {
        int m = mbase + t;
        float delta = g_delta[(size_t)m*DI + d];
        float u     = g_u   [(size_t)m*DI + d];
        const float4* bp = (const float4*)(g_dbc + (size_t)m*DBC_S + DTR);
        float4 B0 = bp[0], B1 = bp[1], B2 = bp[2], B3 = bp[3];
        float Bv[DS] = {B0.x,B0.y,B0.z,B0.w, B1.x,B1.y,B1.z,B1.w,
                        B2.x,B2.y,B2.z,B2.w, B3.x,B3.y,B3.z,B3.w};
        float dbu = delta * u;
        float dA[DS];
        scan_dA(fast, a1, delta, Alog, d, dA);
#pragma unroll
        for (int s = 0; s < DS; s++) {
            h[s] = fmaf(dA[s], h[s], dbu * Bv[s]);
            P[s] *= dA[s];
        }
    }
    size_t o = (((size_t)(b*NC + chunk))*DI + d)*DS;
#pragma unroll
    for (int s = 0; s < DS; s++) { g_hend[o+s] = h[s]; g_pend[o+s] = P[s]; }
}

// ---------------- K6b: sequential chunk combine ----------------------------
__global__ void k_comb() {
    int g = blockIdx.x*256 + threadIdx.x;   // B*DI*DS threads
    int s = g % DS; int d = (g/DS) % DI; int b = g/(DS*DI);
    float h = 0.f;
    for (int c = 0; c < NC; c++) {
        size_t o = (((size_t)(b*NC + c))*DI + d)*DS + s;
        g_hin[o] = h;
        h = fmaf(g_pend[o], h, g_hend[o]);
    }
}

// ---------------- K6c: replay with prefix + y + fused epilogue -------------
__global__ void __launch_bounds__(256)
k_scan2(const float* __restrict__ Alog, const float* __restrict__ Dw) {
    int g = blockIdx.x*256 + threadIdx.x;
    int d = g % DI; int rest = g / DI;
    int chunk = rest % NC; int b = rest / NC;

    float a1; bool fast = fast_check(Alog, d, a1);
    float Dval = Dw[d];
    float h[DS];
    size_t o = (((size_t)(b*NC + chunk))*DI + d)*DS;
#pragma unroll
    for (int s = 0; s < DS; s++) h[s] = g_hin[o + s];

    int mbase = b*LSEQ + chunk*CH;
    for (int t = 0; t < CH; t++) {
        int m = mbase + t;
        float delta = g_delta[(size_t)m*DI + d];
        float u     = g_u   [(size_t)m*DI + d];
        const float4* bp = (const float4*)(g_dbc + (size_t)m*DBC_S + DTR);
        float4 B0 = bp[0], B1 = bp[1], B2 = bp[2], B3 = bp[3];
        const float4* cp = (const float4*)(g_dbc + (size_t)m*DBC_S + DTR + DS);
        float4 C0 = cp[0], C1 = cp[1], C2 = cp[2], C3 = cp[3];
        float Bv[DS] = {B0.x,B0.y,B0.z,B0.w, B1.x,B1.y,B1.z,B1.w,
                        B2.x,B2.y,B2.z,B2.w, B3.x,B3.y,B3.z,B3.w};
        float Cv[DS] = {C0.x,C0.y,C0.z,C0.w, C1.x,C1.y,C1.z,C1.w,
                        C2.x,C2.y,C2.z,C2.w, C3.x,C3.y,C3.z,C3.w};
        float dbu = delta * u;
        float dA[DS];
        scan_dA(fast, a1, delta, Alog, d, dA);
        float y0 = 0.f, y1 = 0.f, y2 = 0.f, y3 = 0.f;
#pragma unroll
        for (int s = 0; s < 4; s++) {
            h[s]    = fmaf(dA[s],    h[s],    dbu*Bv[s]);    y0 = fmaf(h[s],    Cv[s],    y0);
            h[s+4]  = fmaf(dA[s+4],  h[s+4],  dbu*Bv[s+4]);  y1 = fmaf(h[s+4],  Cv[s+4],  y1);
            h[s+8]  = fmaf(dA[s+8],  h[s+8],  dbu*Bv[s+8]);  y2 = fmaf(h[s+8],  Cv[s+8],  y2);
            h[s+12] = fmaf(dA[s+12], h[s+12], dbu*Bv[s+12]); y3 = fmaf(h[s+12], Cv[s+12], y3);
        }
        float y = (y0 + y1) + (y2 + y3);
        float z = g_xz[(size_t)m*(2*DI) + DI + d];
        float sz = z / (1.f + __expf(-z));
        g_y[(size_t)m*DI + d] = (y + u*Dval) * sz;
    }
}

// ---------------- K9: residual + layernorm2 (sums 2 out_proj partials) -----
__global__ void k_ln2(const float* __restrict__ xt,
                      const float* __restrict__ w,
                      const float* __restrict__ bias) {
    int m = blockIdx.x;
    int tid = threadIdx.x;
    const float* xp = xt + (size_t)m * CDIM;
    float v[3]; float s = 0.f, s2 = 0.f;
#pragma unroll
    for (int i = 0; i < 3; i++) {
        int c = tid + i*128;
        float t = xp[c] + g_mo[(size_t)m*CDIM + c]
                        + g_mo[(size_t)MR*CDIM + (size_t)m*CDIM + c];
        v[i] = t; s += t; s2 += t*t;
    }
    __shared__ float sh1[128], sh2[128];
    sh1[tid] = s; sh2[tid] = s2; __syncthreads();
    for (int o = 64; o > 0; o >>= 1) {
        if (tid < o) { sh1[tid] += sh1[tid+o]; sh2[tid] += sh2[tid+o]; }
        __syncthreads();
    }
    float mu  = sh1[0] * (1.f/CDIM);
    float var = sh2[0] * (1.f/CDIM) - mu*mu;
    float rs  = rsqrtf(var + 1e-5f);
#pragma unroll
    for (int i = 0; i < 3; i++) {
        int c = tid + i*128;
        g_res[(size_t)m*CDIM + c] = (v[i]-mu)*rs*w[c] + bias[c];
    }
}

// ---------------- launch ----------------------------------------------------
extern "C" void kernel_launch(void* const* d_in, const int* in_sizes, int n_in,
                              void* d_out, int out_size) {
    const float* x      = (const float*)d_in[0];
    const float* ln1w   = (const float*)d_in[1];
    const float* ln1b   = (const float*)d_in[2];
    const float* ln2w   = (const float*)d_in[3];
    const float* ln2b   = (const float*)d_in[4];
    const float* inpw   = (const float*)d_in[5];   // (1536, 384)
    const float* convw  = (const float*)d_in[6];   // (768, 1, 4)
    const float* convb  = (const float*)d_in[7];
    const float* xprojw = (const float*)d_in[8];   // (56, 768)
    const float* dtw    = (const float*)d_in[9];   // (768, 24)
    const float* dtb    = (const float*)d_in[10];
    const float* alog   = (const float*)d_in[11];  // (768, 16)
    const float* Dd     = (const float*)d_in[12];
    const float* outpw  = (const float*)d_in[13];  // (384, 768)
    float* out = (float*)d_out;

    float *p_xt, *p_xn, *p_xz, *p_y, *p_mo, *p_res;
    __nv_bfloat16 *p_a1, *p_w1, *p_a2, *p_w2;
    cudaGetSymbolAddress((void**)&p_xt,  g_xt);
    cudaGetSymbolAddress((void**)&p_xn,  g_xn);
    cudaGetSymbolAddress((void**)&p_xz,  g_xz);
    cudaGetSymbolAddress((void**)&p_y,   g_y);
    cudaGetSymbolAddress((void**)&p_mo,  g_mo);
    cudaGetSymbolAddress((void**)&p_res, g_res);
    cudaGetSymbolAddress((void**)&p_a1,  g_a1);
    cudaGetSymbolAddress((void**)&p_w1,  g_w1);
    cudaGetSymbolAddress((void**)&p_a2,  g_a2);
    cudaGetSymbolAddress((void**)&p_w2,  g_w2);

    // x (B,C,L) -> g_xt (B,L,C)
    k_tr    <<<dim3(LSEQ/32, CDIM/32, BATCH), dim3(32,8)>>>(x, p_xt, CDIM, LSEQ);
    k_ln1   <<<MR, 128>>>(p_xt, ln1w, ln1b);
    // in_proj: bf16x3 split -> mma.sync GEMM (K3 = 1152)
    k_cvt   <<<(MR*CDIM)/256, 256>>>(p_xn, p_a1, CDIM, 0);
    k_cvt   <<<(2*DI*CDIM)/256, 256>>>(inpw, p_w1, CDIM, 1);
    k_bgemm <<<dim3(2*DI/128, MR/128, 1), 256>>>(p_a1, p_w1, p_xz,
                                                 2*DI, 3*CDIM, 3*CDIM, 0);
    k_conv  <<<(MR*DI)/256, 256>>>(convw, convb);
    k_xproj <<<dim3(MR/64, XSPL), 256>>>(xprojw);
    k_dbcred<<<(MR*DBC_S)/256, 256>>>();
    k_dtproj<<<MR/16, 256>>>(dtw, dtb);
    k_scan1 <<<(BATCH*NC*DI)/256, 256>>>(alog);
    k_comb  <<<(BATCH*DI*DS)/256, 256>>>();
    k_scan2 <<<(BATCH*NC*DI)/256, 256>>>(alog, Dd);
    // out_proj: bf16x3 split -> mma.sync GEMM, K-split 2 (K3 = 2304)
    k_cvt   <<<(MR*DI)/256, 256>>>(p_y, p_a2, DI, 0);
    k_cvt   <<<(CDIM*DI)/256, 256>>>(outpw, p_w2, DI, 1);
    k_bgemm <<<dim3(CDIM/128, MR/128, 2), 256>>>(p_a2, p_w2, p_mo,
                                                 CDIM, 3*DI/2, 3*DI, MR*CDIM);
    k_ln2   <<<MR, 128>>>(p_xt, ln2w, ln2b);
    // g_res (B,L,C) -> out (B,C,L)
    k_tr    <<<dim3(CDIM/32, LSEQ/32, BATCH), dim3(32,8)>>>(p_res, out, LSEQ, CDIM);
}

// round 8
// speedup vs baseline: 1.6900x; 1.6900x over previous
#include <cuda_runtime.h>
#include <cuda_bf16.h>
#include <math.h>
#include <stdint.h>

#define BATCH   2
#define LSEQ    2048
#define CDIM    384
#define DI      768
#define DS      16
#define DTR     24
#define MR      (BATCH*LSEQ)     /* 4096 rows */
#define NC      64               /* scan chunks */
#define CH      (LSEQ/NC)        /* 32 steps per chunk */
#define DBC_S   64               /* padded stride for dbc rows (56 used) */
#define XSPL    8                /* x_proj K-split */

// ---------------- scratch (static device globals; no allocation) ----------
__device__ float g_xt   [MR*CDIM];       // transposed input (B,L,C)
__device__ float g_xz   [MR*2*DI];       // in_proj output (u | z)
__device__ float g_u    [MR*DI];         // conv+silu output
__device__ float g_dbcp [XSPL*MR*DBC_S]; // x_proj K-split partials
__device__ float g_dbc  [MR*DBC_S];      // x_proj output (dt|B|C), padded
__device__ float g_delta[MR*DI];         // softplus(dt_proj)
__device__ float g_mo   [2*MR*CDIM];     // out_proj K-split partials
__device__ float g_res  [MR*CDIM];       // ln2 output (B,L,C) pre-transpose
__device__ float g_hend [BATCH*NC*DI*DS];
__device__ float g_pend [BATCH*NC*DI*DS];
__device__ float g_hin  [BATCH*NC*DI*DS];
// bf16x3 split operands
__device__ __align__(16) __nv_bfloat16 g_a1[MR*3*CDIM];    // in_proj A'  [4096,1152]
__device__ __align__(16) __nv_bfloat16 g_w1[2*DI*3*CDIM];  // in_proj W'  [1536,1152]
__device__ __align__(16) __nv_bfloat16 g_a2[MR*3*DI];      // out_proj A' [4096,2304]
__device__ __align__(16) __nv_bfloat16 g_w2[CDIM*3*DI];    // out_proj W' [384,2304]

// ---------------- helpers ---------------------------------------------------
__device__ __forceinline__ uint32_t smem_u32(const void* p) {
    uint32_t a;
    asm("{ .reg .u64 t; cvta.to.shared.u64 t, %1; cvt.u32.u64 %0, t; }"
        : "=r"(a) : "l"(p));
    return a;
}
#define LDSM4(r0, r1, r2, r3, a) \
    asm volatile("ldmatrix.sync.aligned.m8n8.x4.shared.b16 {%0,%1,%2,%3}, [%4];" \
                 : "=r"(r0), "=r"(r1), "=r"(r2), "=r"(r3) : "r"(a))
#define MMA16816(c, a, b) \
    asm volatile("mma.sync.aligned.m16n8k16.row.col.f32.bf16.bf16.f32 " \
                 "{%0,%1,%2,%3}, {%4,%5,%6,%7}, {%8,%9}, {%0,%1,%2,%3};" \
                 : "+f"((c)[0]), "+f"((c)[1]), "+f"((c)[2]), "+f"((c)[3]) \
                 : "r"((a)[0]), "r"((a)[1]), "r"((a)[2]), "r"((a)[3]), \
                   "r"((b)[0]), "r"((b)[1]))
#define CP_ASYNC16(dst, src) \
    asm volatile("cp.async.cg.shared.global [%0], [%1], 16;" :: "r"(dst), "l"(src))
#define CP_COMMIT() asm volatile("cp.async.commit_group;" ::: "memory")
#define CP_WAIT1()  asm volatile("cp.async.wait_group 1;" ::: "memory")
#define CP_WAIT0()  asm volatile("cp.async.wait_group 0;" ::: "memory")

// ---------------- bf16x3 weight conversion ([hi|hi|lo]) --------------------
__global__ void k_cvt(const float* __restrict__ src, __nv_bfloat16* __restrict__ dst,
                      int K) {
    size_t i = (size_t)blockIdx.x * 256 + threadIdx.x;
    int r = (int)(i / K), k = (int)(i % K);
    float a = src[i];
    __nv_bfloat16 hi = __float2bfloat16(a);
    __nv_bfloat16 lo = __float2bfloat16(a - __bfloat162float(hi));
    size_t base = (size_t)r * 3 * K;
    dst[base + k] = hi; dst[base + K + k] = hi; dst[base + 2*K + k] = lo;
}

// ---------------- bf16 mma.sync GEMM with cp.async 3-stage pipeline --------
// C[z][M,N] = A[M, z*Kl:(z+1)*Kl] * W[N, same]^T ; lda = full K3.
// 128x128 block, 8 warps (4x2), warp tile 32x64, K-chunk 32 bf16.
#define KCH   32
#define SROW  40            /* padded SMEM row, bf16 elems (80B, 16B-mult) */
#define SSTG  (128*SROW)    /* elems per operand per stage */
#define PIPE  3
#define STGB  (2*SSTG*2)    /* bytes per stage block (A then W) */

__global__ void __launch_bounds__(256)
k_bgemm(const __nv_bfloat16* __restrict__ A, const __nv_bfloat16* __restrict__ W,
        float* __restrict__ C, int N, int Kl, int lda, int cstride) {
    extern __shared__ __align__(16) __nv_bfloat16 dsm[];
    uint32_t dynB = smem_u32(dsm);

    int tid = threadIdx.x, lane = tid & 31, wid = tid >> 5;
    int warp_m = wid & 3, warp_n = wid >> 2;          // 4 x 2 warps
    int m0 = blockIdx.y * 128, n0 = blockIdx.x * 128;
    int z = blockIdx.z;
    A += (size_t)z * Kl;
    W += (size_t)z * Kl;
    C += (size_t)z * cstride;

    // cp.async mapping: chunk c in [0,512): row=c>>2, 16B-group cg=c&3
    int c0r = tid >> 2,        c0g = tid & 3;          // chunk tid
    int c1r = (tid + 256) >> 2, c1g = c0g;             // chunk tid+256
    const __nv_bfloat16* A0 = A + (size_t)(m0 + c0r) * lda + c0g * 8;
    const __nv_bfloat16* A1 = A + (size_t)(m0 + c1r) * lda + c1g * 8;
    const __nv_bfloat16* W0 = W + (size_t)(n0 + c0r) * lda + c0g * 8;
    const __nv_bfloat16* W1 = W + (size_t)(n0 + c1r) * lda + c1g * 8;
    uint32_t sd0 = (uint32_t)(c0r * SROW * 2 + c0g * 16);
    uint32_t sd1 = (uint32_t)(c1r * SROW * 2 + c1g * 16);

    // ldmatrix offsets within a stage
    uint32_t aOff = (uint32_t)((warp_m*32 + (lane & 15)) * SROW + ((lane >> 4) & 1) * 8) * 2;
    uint32_t bOff = (uint32_t)((warp_n*64 + (lane & 7) + ((lane >> 4) & 1) * 8) * SROW
                               + ((lane >> 3) & 1) * 8) * 2;

    float acc[2][8][4];
#pragma unroll
    for (int i = 0; i < 2; i++)
#pragma unroll
        for (int j = 0; j < 8; j++)
#pragma unroll
            for (int q = 0; q < 4; q++) acc[i][j][q] = 0.f;

    int NKC = Kl / KCH;

#define LOAD_STAGE(st, kc) do {                                             \
    uint32_t sb = dynB + (uint32_t)(st) * STGB;                             \
    const __nv_bfloat16* off = (const __nv_bfloat16*)0 + (size_t)(kc) * KCH;\
    CP_ASYNC16(sb + sd0,            A0 + (size_t)(kc) * KCH);               \
    CP_ASYNC16(sb + sd1,            A1 + (size_t)(kc) * KCH);               \
    CP_ASYNC16(sb + 2*SSTG + sd0,   W0 + (size_t)(kc) * KCH);               \
    CP_ASYNC16(sb + 2*SSTG + sd1,   W1 + (size_t)(kc) * KCH);               \
    (void)off;                                                              \
} while (0)

    LOAD_STAGE(0, 0); CP_COMMIT();
    LOAD_STAGE(1, 1); CP_COMMIT();

    int st = 0;
    for (int kc = 0; kc < NKC; kc++) {
        if (kc + 1 < NKC) { CP_WAIT1(); } else { CP_WAIT0(); }
        __syncthreads();
        if (kc + 2 < NKC) {
            int nst = st + 2; if (nst >= PIPE) nst -= PIPE;
            LOAD_STAGE(nst, kc + 2); CP_COMMIT();
        }
        uint32_t aS = dynB + (uint32_t)st * STGB + aOff;
        uint32_t bS = dynB + (uint32_t)st * STGB + 2*SSTG + bOff;
#pragma unroll
        for (int ks = 0; ks < 2; ks++) {
            uint32_t af[2][4];
#pragma unroll
            for (int mi = 0; mi < 2; mi++)
                LDSM4(af[mi][0], af[mi][1], af[mi][2], af[mi][3],
                      aS + (uint32_t)(mi*16*SROW + ks*16) * 2);
            uint32_t bf[8][2];
#pragma unroll
            for (int p = 0; p < 4; p++) {
                uint32_t r0, r1, r2, r3;
                LDSM4(r0, r1, r2, r3, bS + (uint32_t)(p*16*SROW + ks*16) * 2);
                bf[2*p][0] = r0;   bf[2*p][1] = r1;
                bf[2*p+1][0] = r2; bf[2*p+1][1] = r3;
            }
#pragma unroll
            for (int mi = 0; mi < 2; mi++)
#pragma unroll
                for (int nj = 0; nj < 8; nj++)
                    MMA16816(acc[mi][nj], af[mi], bf[nj]);
        }
        if (++st >= PIPE) st -= PIPE;
    }

    int rbase = m0 + warp_m*32 + (lane >> 2);
    int cbase = n0 + warp_n*64 + (lane & 3)*2;
#pragma unroll
    for (int mi = 0; mi < 2; mi++) {
#pragma unroll
        for (int nj = 0; nj < 8; nj++) {
            float* cp0 = C + (size_t)(rbase + mi*16) * N + cbase + nj*8;
            float* cp1 = cp0 + 8*N;
            *(float2*)cp0 = make_float2(acc[mi][nj][0], acc[mi][nj][1]);
            *(float2*)cp1 = make_float2(acc[mi][nj][2], acc[mi][nj][3]);
        }
    }
}

// ---------------- K0: tiled transpose  in[z][R][Cc] -> out[z][Cc][R] ------
__global__ void k_tr(const float* __restrict__ in, float* __restrict__ out,
                     int R, int Cc) {
    __shared__ float t[32][33];
    const float* ip = in  + (size_t)blockIdx.z * R * Cc;
    float*       op = out + (size_t)blockIdx.z * R * Cc;
    int c0 = blockIdx.x * 32;
    int r0 = blockIdx.y * 32;
    int lx = threadIdx.x, ly = threadIdx.y;   // 32 x 8
#pragma unroll
    for (int i = 0; i < 4; i++)
        t[ly + i*8][lx] = ip[(size_t)(r0 + ly + i*8) * Cc + c0 + lx];
    __syncthreads();
#pragma unroll
    for (int i = 0; i < 4; i++)
        op[(size_t)(c0 + ly + i*8) * R + r0 + lx] = t[lx][ly + i*8];
}

// ---------------- K1: layernorm over C, writes bf16x3 A' [hi|lo|hi] --------
__global__ void k_ln1(const float* __restrict__ xt,
                      const float* __restrict__ w,
                      const float* __restrict__ bias,
                      __nv_bfloat16* __restrict__ a1) {
    int m = blockIdx.x;
    int tid = threadIdx.x;
    const float* xp = xt + (size_t)m * CDIM;
    float v[3]; float s = 0.f, s2 = 0.f;
#pragma unroll
    for (int i = 0; i < 3; i++) {
        int c = tid + i*128;
        float t = xp[c];
        v[i] = t; s += t; s2 += t*t;
    }
    __shared__ float sh1[128], sh2[128];
    sh1[tid] = s; sh2[tid] = s2; __syncthreads();
    for (int o = 64; o > 0; o >>= 1) {
        if (tid < o) { sh1[tid] += sh1[tid+o]; sh2[tid] += sh2[tid+o]; }
        __syncthreads();
    }
    float mu  = sh1[0] * (1.f/CDIM);
    float var = sh2[0] * (1.f/CDIM) - mu*mu;
    float rs  = rsqrtf(var + 1e-5f);
    __nv_bfloat16* ap = a1 + (size_t)m * 3 * CDIM;
#pragma unroll
    for (int i = 0; i < 3; i++) {
        int c = tid + i*128;
        float t = (v[i]-mu)*rs*w[c] + bias[c];
        __nv_bfloat16 hi = __float2bfloat16(t);
        __nv_bfloat16 lo = __float2bfloat16(t - __bfloat162float(hi));
        ap[c] = hi; ap[CDIM + c] = lo; ap[2*CDIM + c] = hi;
    }
}

// ---------------- K3: causal depthwise conv (D_CONV=4) + bias + silu ------
__global__ void k_conv(const float* __restrict__ cw, const float* __restrict__ cb) {
    int idx = blockIdx.x*256 + threadIdx.x;
    int d = idx % DI, m = idx / DI;
    int l = m % LSEQ;
    float acc = cb[d];
#pragma unroll
    for (int j = 0; j < 4; j++) {
        int ll = l - 3 + j;
        if (ll >= 0)
            acc = fmaf(cw[d*4+j], g_xz[(size_t)(m-3+j)*(2*DI) + d], acc);
    }
    float sg = 1.f / (1.f + __expf(-acc));
    g_u[idx] = acc * sg;
}

// ---------------- K4: x_proj partial  (K-split via blockIdx.y) -------------
__global__ void __launch_bounds__(256)
k_xproj(const float* __restrict__ W) {
    __shared__ float us[32][68];   // [k][m]
    __shared__ float ws[56][33];   // [n][k]
    int tid = threadIdx.x;
    int m0 = blockIdx.x * 64;
    int z  = blockIdx.y;
    int kbase = z * (DI/XSPL);     // 96
    int n  = tid & 63, mg = tid >> 6;
    int nn = (n < 56) ? n : 55;
    float acc[16];
#pragma unroll
    for (int i = 0; i < 16; i++) acc[i] = 0.f;

    for (int k0 = kbase; k0 < kbase + DI/XSPL; k0 += 32) {
        __syncthreads();
        for (int v = tid; v < 512; v += 256) {
            int mr = v >> 3, kb = v & 7;
            float4 t = *(const float4*)(g_u + (size_t)(m0+mr)*DI + k0 + kb*4);
            us[kb*4+0][mr] = t.x; us[kb*4+1][mr] = t.y;
            us[kb*4+2][mr] = t.z; us[kb*4+3][mr] = t.w;
        }
        for (int v = tid; v < 448; v += 256) {
            int nr = v >> 3, kb = v & 7;
            float4 t = *(const float4*)(W + (size_t)nr*DI + k0 + kb*4);
            ws[nr][kb*4+0] = t.x; ws[nr][kb*4+1] = t.y;
            ws[nr][kb*4+2] = t.z; ws[nr][kb*4+3] = t.w;
        }
        __syncthreads();
#pragma unroll 4
        for (int kk = 0; kk < 32; kk++) {
            float wv = ws[nn][kk];
            float4 u0 = *(const float4*)&us[kk][mg*16+0];
            float4 u1 = *(const float4*)&us[kk][mg*16+4];
            float4 u2 = *(const float4*)&us[kk][mg*16+8];
            float4 u3 = *(const float4*)&us[kk][mg*16+12];
            acc[0]  = fmaf(u0.x, wv, acc[0]);  acc[1]  = fmaf(u0.y, wv, acc[1]);
            acc[2]  = fmaf(u0.z, wv, acc[2]);  acc[3]  = fmaf(u0.w, wv, acc[3]);
            acc[4]  = fmaf(u1.x, wv, acc[4]);  acc[5]  = fmaf(u1.y, wv, acc[5]);
            acc[6]  = fmaf(u1.z, wv, acc[6]);  acc[7]  = fmaf(u1.w, wv, acc[7]);
            acc[8]  = fmaf(u2.x, wv, acc[8]);  acc[9]  = fmaf(u2.y, wv, acc[9]);
            acc[10] = fmaf(u2.z, wv, acc[10]); acc[11] = fmaf(u2.w, wv, acc[11]);
            acc[12] = fmaf(u3.x, wv, acc[12]); acc[13] = fmaf(u3.y, wv, acc[13]);
            acc[14] = fmaf(u3.z, wv, acc[14]); acc[15] = fmaf(u3.w, wv, acc[15]);
        }
    }
    if (n < 56) {
#pragma unroll
        for (int i = 0; i < 16; i++)
            g_dbcp[((size_t)z*MR + m0 + mg*16 + i)*DBC_S + n] = acc[i];
    }
}

// ---------------- K4b: reduce the K-split partials -------------------------
__global__ void k_dbcred() {
    size_t i = (size_t)blockIdx.x*256 + threadIdx.x;    // < MR*DBC_S
    float s = 0.f;
#pragma unroll
    for (int z = 0; z < XSPL; z++) s += g_dbcp[(size_t)z*MR*DBC_S + i];
    g_dbc[i] = s;
}

// ---------------- K5: dt_proj + softplus -> delta --------------------------
__global__ void k_dtproj(const float* __restrict__ W, const float* __restrict__ bias) {
    __shared__ float sdt[16][24];
    int tid = threadIdx.x;
    int m0 = blockIdx.x * 16;
    for (int idx = tid; idx < 16*24; idx += 256) {
        int mi = idx / 24, r = idx % 24;
        sdt[mi][r] = g_dbc[(size_t)(m0+mi)*DBC_S + r];
    }
    __syncthreads();
    for (int d = tid; d < DI; d += 256) {
        float wr[24];
#pragma unroll
        for (int r = 0; r < 24; r++) wr[r] = W[d*24 + r];
        float bz = bias[d];
        for (int mi = 0; mi < 16; mi++) {
            float a = bz;
#pragma unroll
            for (int r = 0; r < 24; r++) a = fmaf(sdt[mi][r], wr[r], a);
            float sp = (a > 20.f) ? a : log1pf(expf(a));
            g_delta[(size_t)(m0+mi)*DI + d] = sp;
        }
    }
}

// ---------------- scan helpers ---------------------------------------------
__device__ __forceinline__ void scan_dA(bool fast, float a1, float delta,
                                        const float* __restrict__ Alog, int d,
                                        float dA[DS]) {
    if (fast) {
        float p = __expf(delta * a1);      // dA[s] = p^(s+1)
        dA[0] = p;
#pragma unroll
        for (int s = 1; s < DS; s++) dA[s] = dA[s-1] * p;
    } else {
#pragma unroll
        for (int s = 0; s < DS; s++)
            dA[s] = __expf(delta * (-__expf(Alog[d*DS + s])));
    }
}

__device__ __forceinline__ bool fast_check(const float* __restrict__ Alog,
                                           int d, float& a1) {
    a1 = -__expf(Alog[d*DS + 0]);
    bool fast = true;
#pragma unroll
    for (int s = 0; s < DS; s++) {
        float as = -__expf(Alog[d*DS + s]);
        fast = fast && (fabsf(as - (float)(s+1)*a1) <= 1e-4f*fabsf(as) + 1e-12f);
    }
    return fast;
}

// ---------------- K6a: chunk-local scan (one block per (b,chunk)) ----------
__global__ void __launch_bounds__(768)
k_scan1(const float* __restrict__ Alog) {
    __shared__ float sB[CH*DS];
    int blk = blockIdx.x;
    int chunk = blk & (NC-1), b = blk / NC;
    int d = threadIdx.x;
    int mbase = b*LSEQ + chunk*CH;
    if (d < CH*DS) {
        int t = d >> 4, s = d & 15;
        sB[d] = g_dbc[(size_t)(mbase+t)*DBC_S + DTR + s];
    }
    __syncthreads();

    float a1; bool fast = fast_check(Alog, d, a1);
    float h[DS], P[DS];
#pragma unroll
    for (int s = 0; s < DS; s++) { h[s] = 0.f; P[s] = 1.f; }

    float delta = g_delta[(size_t)mbase*DI + d];
    float u     = g_u   [(size_t)mbase*DI + d];
    for (int t = 0; t < CH; t++) {
        float nd = 0.f, nu = 0.f;
        if (t + 1 < CH) {
            nd = g_delta[(size_t)(mbase+t+1)*DI + d];
            nu = g_u   [(size_t)(mbase+t+1)*DI + d];
        }
        float dbu = delta * u;
        float dA[DS];
        scan_dA(fast, a1, delta, Alog, d, dA);
        const float* Bt = &sB[t*DS];
#pragma unroll
        for (int s = 0; s < DS; s++) {
            h[s] = fmaf(dA[s], h[s], dbu * Bt[s]);
            P[s] *= dA[s];
        }
        delta = nd; u = nu;
    }
    size_t o = (((size_t)(b*NC + chunk))*DI + d)*DS;
#pragma unroll
    for (int s = 0; s < DS; s++) { g_hend[o+s] = h[s]; g_pend[o+s] = P[s]; }
}

// ---------------- K6b: sequential chunk combine ----------------------------
__global__ void k_comb() {
    int g = blockIdx.x*256 + threadIdx.x;   // B*DI*DS threads
    int s = g % DS; int d = (g/DS) % DI; int b = g/(DS*DI);
    float h = 0.f;
    for (int c = 0; c < NC; c++) {
        size_t o = (((size_t)(b*NC + c))*DI + d)*DS + s;
        g_hin[o] = h;
        h = fmaf(g_pend[o], h, g_hend[o]);
    }
}

// ---------------- K6c: replay + epilogue, writes bf16x3 A' [hi|lo|hi] ------
__global__ void __launch_bounds__(768)
k_scan2(const float* __restrict__ Alog, const float* __restrict__ Dw,
        __nv_bfloat16* __restrict__ a2) {
    __shared__ float sB[CH*DS];
    __shared__ float sC[CH*DS];
    int blk = blockIdx.x;
    int chunk = blk & (NC-1), b = blk / NC;
    int d = threadIdx.x;
    int mbase = b*LSEQ + chunk*CH;
    if (d < CH*DS) {
        int t = d >> 4, s = d & 15;
        sB[d] = g_dbc[(size_t)(mbase+t)*DBC_S + DTR + s];
        sC[d] = g_dbc[(size_t)(mbase+t)*DBC_S + DTR + DS + s];
    }
    __syncthreads();

    float a1; bool fast = fast_check(Alog, d, a1);
    float Dval = Dw[d];
    float h[DS];
    size_t o = (((size_t)(b*NC + chunk))*DI + d)*DS;
#pragma unroll
    for (int s = 0; s < DS; s++) h[s] = g_hin[o + s];

    float delta = g_delta[(size_t)mbase*DI + d];
    float u     = g_u   [(size_t)mbase*DI + d];
    for (int t = 0; t < CH; t++) {
        int m = mbase + t;
        float nd = 0.f, nu = 0.f;
        if (t + 1 < CH) {
            nd = g_delta[(size_t)(m+1)*DI + d];
            nu = g_u   [(size_t)(m+1)*DI + d];
        }
        float dbu = delta * u;
        float dA[DS];
        scan_dA(fast, a1, delta, Alog, d, dA);
        const float* Bt = &sB[t*DS];
        const float* Ct = &sC[t*DS];
        float y0 = 0.f, y1 = 0.f, y2 = 0.f, y3 = 0.f;
#pragma unroll
        for (int s = 0; s < 4; s++) {
            h[s]    = fmaf(dA[s],    h[s],    dbu*Bt[s]);    y0 = fmaf(h[s],    Ct[s],    y0);
            h[s+4]  = fmaf(dA[s+4],  h[s+4],  dbu*Bt[s+4]);  y1 = fmaf(h[s+4],  Ct[s+4],  y1);
            h[s+8]  = fmaf(dA[s+8],  h[s+8],  dbu*Bt[s+8]);  y2 = fmaf(h[s+8],  Ct[s+8],  y2);
            h[s+12] = fmaf(dA[s+12], h[s+12], dbu*Bt[s+12]); y3 = fmaf(h[s+12], Ct[s+12], y3);
        }
        float y = (y0 + y1) + (y2 + y3);
        float zz = g_xz[(size_t)m*(2*DI) + DI + d];
        float sz = zz / (1.f + __expf(-zz));
        float yo = (y + u*Dval) * sz;
        __nv_bfloat16 hi = __float2bfloat16(yo);
        __nv_bfloat16 lo = __float2bfloat16(yo - __bfloat162float(hi));
        __nv_bfloat16* ap = a2 + (size_t)m * 3 * DI;
        ap[d] = hi; ap[DI + d] = lo; ap[2*DI + d] = hi;
        delta = nd; u = nu;
    }
}

// ---------------- K9: residual + layernorm2 (sums 2 out_proj partials) -----
__global__ void k_ln2(const float* __restrict__ xt,
                      const float* __restrict__ w,
                      const float* __restrict__ bias) {
    int m = blockIdx.x;
    int tid = threadIdx.x;
    const float* xp = xt + (size_t)m * CDIM;
    float v[3]; float s = 0.f, s2 = 0.f;
#pragma unroll
    for (int i = 0; i < 3; i++) {
        int c = tid + i*128;
        float t = xp[c] + g_mo[(size_t)m*CDIM + c]
                        + g_mo[(size_t)MR*CDIM + (size_t)m*CDIM + c];
        v[i] = t; s += t; s2 += t*t;
    }
    __shared__ float sh1[128], sh2[128];
    sh1[tid] = s; sh2[tid] = s2; __syncthreads();
    for (int o = 64; o > 0; o >>= 1) {
        if (tid < o) { sh1[tid] += sh1[tid+o]; sh2[tid] += sh2[tid+o]; }
        __syncthreads();
    }
    float mu  = sh1[0] * (1.f/CDIM);
    float var = sh2[0] * (1.f/CDIM) - mu*mu;
    float rs  = rsqrtf(var + 1e-5f);
#pragma unroll
    for (int i = 0; i < 3; i++) {
        int c = tid + i*128;
        g_res[(size_t)m*CDIM + c] = (v[i]-mu)*rs*w[c] + bias[c];
    }
}

// ---------------- launch ----------------------------------------------------
extern "C" void kernel_launch(void* const* d_in, const int* in_sizes, int n_in,
                              void* d_out, int out_size) {
    const float* x      = (const float*)d_in[0];
    const float* ln1w   = (const float*)d_in[1];
    const float* ln1b   = (const float*)d_in[2];
    const float* ln2w   = (const float*)d_in[3];
    const float* ln2b   = (const float*)d_in[4];
    const float* inpw   = (const float*)d_in[5];   // (1536, 384)
    const float* convw  = (const float*)d_in[6];   // (768, 1, 4)
    const float* convb  = (const float*)d_in[7];
    const float* xprojw = (const float*)d_in[8];   // (56, 768)
    const float* dtw    = (const float*)d_in[9];   // (768, 24)
    const float* dtb    = (const float*)d_in[10];
    const float* alog   = (const float*)d_in[11];  // (768, 16)
    const float* Dd     = (const float*)d_in[12];
    const float* outpw  = (const float*)d_in[13];  // (384, 768)
    float* out = (float*)d_out;

    float *p_xt, *p_xz, *p_mo, *p_res;
    __nv_bfloat16 *p_a1, *p_w1, *p_a2, *p_w2;
    cudaGetSymbolAddress((void**)&p_xt,  g_xt);
    cudaGetSymbolAddress((void**)&p_xz,  g_xz);
    cudaGetSymbolAddress((void**)&p_mo,  g_mo);
    cudaGetSymbolAddress((void**)&p_res, g_res);
    cudaGetSymbolAddress((void**)&p_a1,  g_a1);
    cudaGetSymbolAddress((void**)&p_w1,  g_w1);
    cudaGetSymbolAddress((void**)&p_a2,  g_a2);
    cudaGetSymbolAddress((void**)&p_w2,  g_w2);

    static const int BG_SMEM = PIPE * STGB;   // 61440 bytes
    cudaFuncSetAttribute(k_bgemm, cudaFuncAttributeMaxDynamicSharedMemorySize, BG_SMEM);

    // x (B,C,L) -> g_xt (B,L,C)
    k_tr    <<<dim3(LSEQ/32, CDIM/32, BATCH), dim3(32,8)>>>(x, p_xt, CDIM, LSEQ);
    k_ln1   <<<MR, 128>>>(p_xt, ln1w, ln1b, p_a1);
    // in_proj: bf16x3 -> mma.sync GEMM with cp.async pipeline (K3 = 1152)
    k_cvt   <<<(2*DI*CDIM)/256, 256>>>(inpw, p_w1, CDIM);
    k_bgemm <<<dim3(2*DI/128, MR/128, 1), 256, BG_SMEM>>>(p_a1, p_w1, p_xz,
                                                          2*DI, 3*CDIM, 3*CDIM, 0);
    k_conv  <<<(MR*DI)/256, 256>>>(convw, convb);
    k_xproj <<<dim3(MR/64, XSPL), 256>>>(xprojw);
    k_dbcred<<<(MR*DBC_S)/256, 256>>>();
    k_dtproj<<<MR/16, 256>>>(dtw, dtb);
    k_scan1 <<<BATCH*NC, 768>>>(alog);
    k_comb  <<<(BATCH*DI*DS)/256, 256>>>();
    k_scan2 <<<BATCH*NC, 768>>>(alog, Dd, p_a2);
    // out_proj: bf16x3 -> mma.sync GEMM, K-split 2 (K3 = 2304, Kl = 1152)
    k_cvt   <<<(CDIM*DI)/256, 256>>>(outpw, p_w2, DI);
    k_bgemm <<<dim3(CDIM/128, MR/128, 2), 256, BG_SMEM>>>(p_a2, p_w2, p_mo,
                                                          CDIM, 3*DI/2, 3*DI, MR*CDIM);
    k_ln2   <<<MR, 128>>>(p_xt, ln2w, ln2b);
    // g_res (B,L,C) -> out (B,C,L)
    k_tr    <<<dim3(CDIM/32, LSEQ/32, BATCH), dim3(32,8)>>>(p_res, out, LSEQ, CDIM);
}

// round 11
// speedup vs baseline: 2.0554x; 1.2162x over previous
#include <cuda_runtime.h>
#include <cuda_bf16.h>
#include <math.h>
#include <stdint.h>

#define BATCH   2
#define LSEQ    2048
#define CDIM    384
#define DI      768
#define DS      16
#define DTR     24
#define MR      (BATCH*LSEQ)     /* 4096 rows */
#define NC      64               /* scan chunks */
#define CH      (LSEQ/NC)        /* 32 steps per chunk */
#define DBC_S   64               /* padded stride for dbc rows (56 used) */
#define XSPL    8                /* x_proj K-split */

// ---------------- scratch (static device globals; no allocation) ----------
__device__ float g_xt   [MR*CDIM];       // transposed input (B,L,C)
__device__ float g_xz   [MR*2*DI];       // in_proj output (u | z)
__device__ float g_u    [MR*DI];         // conv+silu output
__device__ float g_dbcp [XSPL*MR*DBC_S]; // x_proj K-split partials
__device__ float g_dbc  [MR*DBC_S];      // x_proj output (dt|B|C), padded
__device__ float g_delta[MR*DI];         // softplus(dt_proj)
__device__ float g_mo   [2*MR*CDIM];     // out_proj K-split partials
__device__ float g_res  [MR*CDIM];       // ln2 output (B,L,C) pre-transpose
__device__ float g_hend [BATCH*NC*DI*DS];
__device__ float g_pend [BATCH*NC*DI*DS];
__device__ float g_hin  [BATCH*NC*DI*DS];
// bf16x2 split operands: A' = [hi | lo], W' = [hi | hi]
__device__ __align__(16) __nv_bfloat16 g_a1[MR*2*CDIM];    // in_proj A'  [4096,768]
__device__ __align__(16) __nv_bfloat16 g_w1[2*DI*2*CDIM];  // in_proj W'  [1536,768]
__device__ __align__(16) __nv_bfloat16 g_a2[MR*2*DI];      // out_proj A' [4096,1536]
__device__ __align__(16) __nv_bfloat16 g_w2[CDIM*2*DI];    // out_proj W' [384,1536]

// ---------------- helpers ---------------------------------------------------
__device__ __forceinline__ uint32_t smem_u32(const void* p) {
    uint32_t a;
    asm("{ .reg .u64 t; cvta.to.shared.u64 t, %1; cvt.u32.u64 %0, t; }"
        : "=r"(a) : "l"(p));
    return a;
}
#define LDSM4(r0, r1, r2, r3, a) \
    asm volatile("ldmatrix.sync.aligned.m8n8.x4.shared.b16 {%0,%1,%2,%3}, [%4];" \
                 : "=r"(r0), "=r"(r1), "=r"(r2), "=r"(r3) : "r"(a))
#define MMA16816(c, a, b) \
    asm volatile("mma.sync.aligned.m16n8k16.row.col.f32.bf16.bf16.f32 " \
                 "{%0,%1,%2,%3}, {%4,%5,%6,%7}, {%8,%9}, {%0,%1,%2,%3};" \
                 : "+f"((c)[0]), "+f"((c)[1]), "+f"((c)[2]), "+f"((c)[3]) \
                 : "r"((a)[0]), "r"((a)[1]), "r"((a)[2]), "r"((a)[3]), \
                   "r"((b)[0]), "r"((b)[1]))
#define CP_ASYNC16(dst, src) \
    asm volatile("cp.async.cg.shared.global [%0], [%1], 16;" :: "r"(dst), "l"(src))
#define CP_COMMIT() asm volatile("cp.async.commit_group;" ::: "memory")
#define CP_WAIT2()  asm volatile("cp.async.wait_group 2;" ::: "memory")
#define CP_WAIT1()  asm volatile("cp.async.wait_group 1;" ::: "memory")
#define CP_WAIT0()  asm volatile("cp.async.wait_group 0;" ::: "memory")

// ---------------- bf16x2 weight conversion ([hi|hi]) -----------------------
__global__ void k_cvt(const float* __restrict__ src, __nv_bfloat16* __restrict__ dst,
                      int K) {
    size_t i = (size_t)blockIdx.x * 256 + threadIdx.x;
    int r = (int)(i / K), k = (int)(i % K);
    float a = src[i];
    __nv_bfloat16 hi = __float2bfloat16(a);
    size_t base = (size_t)r * 2 * K;
    dst[base + k] = hi; dst[base + K + k] = hi;
}

// ---------------- bf16 mma.sync GEMM, cp.async 4-stage pipeline ------------
// C[z][M,N] = A[M, z*Kl:(z+1)*Kl] * W[N, same]^T ; lda = full K2.
// 128x128 block, 8 warps (4x2), warp tile 32x64, K-chunk 32 bf16.
#define KCH   32
#define SROW  40            /* padded SMEM row, bf16 elems (80B, 16B-mult) */
#define SSTG  (128*SROW)    /* elems per operand per stage */
#define PIPE  4
#define STGB  (2*SSTG*2)    /* bytes per stage block (A then W) */

__global__ void __launch_bounds__(256, 2)
k_bgemm(const __nv_bfloat16* __restrict__ A, const __nv_bfloat16* __restrict__ W,
        float* __restrict__ C, int N, int Kl, int lda, int cstride) {
    extern __shared__ __align__(16) __nv_bfloat16 dsm[];
    uint32_t dynB = smem_u32(dsm);

    int tid = threadIdx.x, lane = tid & 31, wid = tid >> 5;
    int warp_m = wid & 3, warp_n = wid >> 2;          // 4 x 2 warps
    int m0 = blockIdx.y * 128, n0 = blockIdx.x * 128;
    int z = blockIdx.z;
    A += (size_t)z * Kl;
    W += (size_t)z * Kl;
    C += (size_t)z * cstride;

    // cp.async mapping: chunk elem c in [0,512): row=c>>2, 16B-group cg=c&3
    int c0r = tid >> 2,         c0g = tid & 3;
    int c1r = (tid + 256) >> 2, c1g = c0g;
    const __nv_bfloat16* A0 = A + (size_t)(m0 + c0r) * lda + c0g * 8;
    const __nv_bfloat16* A1 = A + (size_t)(m0 + c1r) * lda + c1g * 8;
    const __nv_bfloat16* W0 = W + (size_t)(n0 + c0r) * lda + c0g * 8;
    const __nv_bfloat16* W1 = W + (size_t)(n0 + c1r) * lda + c1g * 8;
    uint32_t sd0 = (uint32_t)(c0r * SROW * 2 + c0g * 16);
    uint32_t sd1 = (uint32_t)(c1r * SROW * 2 + c1g * 16);

    // ldmatrix offsets within a stage
    uint32_t aOff = (uint32_t)((warp_m*32 + (lane & 15)) * SROW + ((lane >> 4) & 1) * 8) * 2;
    uint32_t bOff = (uint32_t)((warp_n*64 + (lane & 7) + ((lane >> 4) & 1) * 8) * SROW
                               + ((lane >> 3) & 1) * 8) * 2;

    float acc[2][8][4];
#pragma unroll
    for (int i = 0; i < 2; i++)
#pragma unroll
        for (int j = 0; j < 8; j++)
#pragma unroll
            for (int q = 0; q < 4; q++) acc[i][j][q] = 0.f;

    int NKC = Kl / KCH;

#define LOAD_STAGE(st, kc) do {                                             \
    uint32_t sb = dynB + (uint32_t)(st) * STGB;                             \
    CP_ASYNC16(sb + sd0,            A0 + (size_t)(kc) * KCH);               \
    CP_ASYNC16(sb + sd1,            A1 + (size_t)(kc) * KCH);               \
    CP_ASYNC16(sb + 2*SSTG + sd0,   W0 + (size_t)(kc) * KCH);               \
    CP_ASYNC16(sb + 2*SSTG + sd1,   W1 + (size_t)(kc) * KCH);               \
} while (0)

    LOAD_STAGE(0, 0); CP_COMMIT();
    LOAD_STAGE(1, 1); CP_COMMIT();
    LOAD_STAGE(2, 2); CP_COMMIT();

    int st = 0;
    for (int kc = 0; kc < NKC; kc++) {
        if (kc < NKC - 2)      { CP_WAIT2(); }
        else if (kc == NKC - 2){ CP_WAIT1(); }
        else                   { CP_WAIT0(); }
        __syncthreads();
        if (kc + 3 < NKC) {
            int nst = st + 3; if (nst >= PIPE) nst -= PIPE;
            LOAD_STAGE(nst, kc + 3); CP_COMMIT();
        }
        uint32_t aS = dynB + (uint32_t)st * STGB + aOff;
        uint32_t bS = dynB + (uint32_t)st * STGB + 2*SSTG + bOff;
#pragma unroll
        for (int ks = 0; ks < 2; ks++) {
            uint32_t af[2][4];
#pragma unroll
            for (int mi = 0; mi < 2; mi++)
                LDSM4(af[mi][0], af[mi][1], af[mi][2], af[mi][3],
                      aS + (uint32_t)(mi*16*SROW + ks*16) * 2);
            uint32_t bf[8][2];
#pragma unroll
            for (int p = 0; p < 4; p++) {
                uint32_t r0, r1, r2, r3;
                LDSM4(r0, r1, r2, r3, bS + (uint32_t)(p*16*SROW + ks*16) * 2);
                bf[2*p][0] = r0;   bf[2*p][1] = r1;
                bf[2*p+1][0] = r2; bf[2*p+1][1] = r3;
            }
#pragma unroll
            for (int mi = 0; mi < 2; mi++)
#pragma unroll
                for (int nj = 0; nj < 8; nj++)
                    MMA16816(acc[mi][nj], af[mi], bf[nj]);
        }
        if (++st >= PIPE) st -= PIPE;
    }

    int rbase = m0 + warp_m*32 + (lane >> 2);
    int cbase = n0 + warp_n*64 + (lane & 3)*2;
#pragma unroll
    for (int mi = 0; mi < 2; mi++) {
#pragma unroll
        for (int nj = 0; nj < 8; nj++) {
            float* cp0 = C + (size_t)(rbase + mi*16) * N + cbase + nj*8;
            float* cp1 = cp0 + 8*N;
            *(float2*)cp0 = make_float2(acc[mi][nj][0], acc[mi][nj][1]);
            *(float2*)cp1 = make_float2(acc[mi][nj][2], acc[mi][nj][3]);
        }
    }
}

// ---------------- K0: tiled transpose  in[z][R][Cc] -> out[z][Cc][R] ------
__global__ void k_tr(const float* __restrict__ in, float* __restrict__ out,
                     int R, int Cc) {
    __shared__ float t[32][33];
    const float* ip = in  + (size_t)blockIdx.z * R * Cc;
    float*       op = out + (size_t)blockIdx.z * R * Cc;
    int c0 = blockIdx.x * 32;
    int r0 = blockIdx.y * 32;
    int lx = threadIdx.x, ly = threadIdx.y;   // 32 x 8
#pragma unroll
    for (int i = 0; i < 4; i++)
        t[ly + i*8][lx] = ip[(size_t)(r0 + ly + i*8) * Cc + c0 + lx];
    __syncthreads();
#pragma unroll
    for (int i = 0; i < 4; i++)
        op[(size_t)(c0 + ly + i*8) * R + r0 + lx] = t[lx][ly + i*8];
}

// ---------------- K1: layernorm over C, writes bf16x2 A' [hi|lo] -----------
__global__ void k_ln1(const float* __restrict__ xt,
                      const float* __restrict__ w,
                      const float* __restrict__ bias,
                      __nv_bfloat16* __restrict__ a1) {
    int m = blockIdx.x;
    int tid = threadIdx.x;
    const float* xp = xt + (size_t)m * CDIM;
    float v[3]; float s = 0.f, s2 = 0.f;
#pragma unroll
    for (int i = 0; i < 3; i++) {
        int c = tid + i*128;
        float t = xp[c];
        v[i] = t; s += t; s2 += t*t;
    }
    __shared__ float sh1[128], sh2[128];
    sh1[tid] = s; sh2[tid] = s2; __syncthreads();
    for (int o = 64; o > 0; o >>= 1) {
        if (tid < o) { sh1[tid] += sh1[tid+o]; sh2[tid] += sh2[tid+o]; }
        __syncthreads();
    }
    float mu  = sh1[0] * (1.f/CDIM);
    float var = sh2[0] * (1.f/CDIM) - mu*mu;
    float rs  = rsqrtf(var + 1e-5f);
    __nv_bfloat16* ap = a1 + (size_t)m * 2 * CDIM;
#pragma unroll
    for (int i = 0; i < 3; i++) {
        int c = tid + i*128;
        float t = (v[i]-mu)*rs*w[c] + bias[c];
        __nv_bfloat16 hi = __float2bfloat16(t);
        __nv_bfloat16 lo = __float2bfloat16(t - __bfloat162float(hi));
        ap[c] = hi; ap[CDIM + c] = lo;
    }
}

// ---------------- K3: causal depthwise conv (D_CONV=4) + bias + silu ------
__global__ void k_conv(const float* __restrict__ cw, const float* __restrict__ cb) {
    int idx = blockIdx.x*256 + threadIdx.x;
    int d = idx % DI, m = idx / DI;
    int l = m % LSEQ;
    float acc = cb[d];
#pragma unroll
    for (int j = 0; j < 4; j++) {
        int ll = l - 3 + j;
        if (ll >= 0)
            acc = fmaf(cw[d*4+j], g_xz[(size_t)(m-3+j)*(2*DI) + d], acc);
    }
    float sg = 1.f / (1.f + __expf(-acc));
    g_u[idx] = acc * sg;
}

// ---------------- K4: x_proj partial  (K-split via blockIdx.y) -------------
__global__ void __launch_bounds__(256)
k_xproj(const float* __restrict__ W) {
    __shared__ float us[32][68];   // [k][m]
    __shared__ float ws[56][33];   // [n][k]
    int tid = threadIdx.x;
    int m0 = blockIdx.x * 64;
    int z  = blockIdx.y;
    int kbase = z * (DI/XSPL);     // 96
    int n  = tid & 63, mg = tid >> 6;
    int nn = (n < 56) ? n : 55;
    float acc[16];
#pragma unroll
    for (int i = 0; i < 16; i++) acc[i] = 0.f;

    for (int k0 = kbase; k0 < kbase + DI/XSPL; k0 += 32) {
        __syncthreads();
        for (int v = tid; v < 512; v += 256) {
            int mr = v >> 3, kb = v & 7;
            float4 t = *(const float4*)(g_u + (size_t)(m0+mr)*DI + k0 + kb*4);
            us[kb*4+0][mr] = t.x; us[kb*4+1][mr] = t.y;
            us[kb*4+2][mr] = t.z; us[kb*4+3][mr] = t.w;
        }
        for (int v = tid; v < 448; v += 256) {
            int nr = v >> 3, kb = v & 7;
            float4 t = *(const float4*)(W + (size_t)nr*DI + k0 + kb*4);
            ws[nr][kb*4+0] = t.x; ws[nr][kb*4+1] = t.y;
            ws[nr][kb*4+2] = t.z; ws[nr][kb*4+3] = t.w;
        }
        __syncthreads();
#pragma unroll 4
        for (int kk = 0; kk < 32; kk++) {
            float wv = ws[nn][kk];
            float4 u0 = *(const float4*)&us[kk][mg*16+0];
            float4 u1 = *(const float4*)&us[kk][mg*16+4];
            float4 u2 = *(const float4*)&us[kk][mg*16+8];
            float4 u3 = *(const float4*)&us[kk][mg*16+12];
            acc[0]  = fmaf(u0.x, wv, acc[0]);  acc[1]  = fmaf(u0.y, wv, acc[1]);
            acc[2]  = fmaf(u0.z, wv, acc[2]);  acc[3]  = fmaf(u0.w, wv, acc[3]);
            acc[4]  = fmaf(u1.x, wv, acc[4]);  acc[5]  = fmaf(u1.y, wv, acc[5]);
            acc[6]  = fmaf(u1.z, wv, acc[6]);  acc[7]  = fmaf(u1.w, wv, acc[7]);
            acc[8]  = fmaf(u2.x, wv, acc[8]);  acc[9]  = fmaf(u2.y, wv, acc[9]);
            acc[10] = fmaf(u2.z, wv, acc[10]); acc[11] = fmaf(u2.w, wv, acc[11]);
            acc[12] = fmaf(u3.x, wv, acc[12]); acc[13] = fmaf(u3.y, wv, acc[13]);
            acc[14] = fmaf(u3.z, wv, acc[14]); acc[15] = fmaf(u3.w, wv, acc[15]);
        }
    }
    if (n < 56) {
#pragma unroll
        for (int i = 0; i < 16; i++)
            g_dbcp[((size_t)z*MR + m0 + mg*16 + i)*DBC_S + n] = acc[i];
    }
}

// ---------------- K4b: reduce the K-split partials -------------------------
__global__ void k_dbcred() {
    size_t i = (size_t)blockIdx.x*256 + threadIdx.x;    // < MR*DBC_S
    float s = 0.f;
#pragma unroll
    for (int z = 0; z < XSPL; z++) s += g_dbcp[(size_t)z*MR*DBC_S + i];
    g_dbc[i] = s;
}

// ---------------- K5: dt_proj + softplus -> delta --------------------------
__global__ void k_dtproj(const float* __restrict__ W, const float* __restrict__ bias) {
    __shared__ float sdt[16][24];
    int tid = threadIdx.x;
    int m0 = blockIdx.x * 16;
    for (int idx = tid; idx < 16*24; idx += 256) {
        int mi = idx / 24, r = idx % 24;
        sdt[mi][r] = g_dbc[(size_t)(m0+mi)*DBC_S + r];
    }
    __syncthreads();
    for (int d = tid; d < DI; d += 256) {
        float wr[24];
#pragma unroll
        for (int r = 0; r < 24; r++) wr[r] = W[d*24 + r];
        float bz = bias[d];
        for (int mi = 0; mi < 16; mi++) {
            float a = bz;
#pragma unroll
            for (int r = 0; r < 24; r++) a = fmaf(sdt[mi][r], wr[r], a);
            float sp = (a > 20.f) ? a : log1pf(expf(a));
            g_delta[(size_t)(m0+mi)*DI + d] = sp;
        }
    }
}

// ---------------- scan helpers ---------------------------------------------
__device__ __forceinline__ void scan_dA(bool fast, float a1, float delta,
                                        const float* __restrict__ Alog, int d,
                                        float dA[DS]) {
    if (fast) {
        float p = __expf(delta * a1);      // dA[s] = p^(s+1)
        dA[0] = p;
#pragma unroll
        for (int s = 1; s < DS; s++) dA[s] = dA[s-1] * p;
    } else {
#pragma unroll
        for (int s = 0; s < DS; s++)
            dA[s] = __expf(delta * (-__expf(Alog[d*DS + s])));
    }
}

__device__ __forceinline__ bool fast_check(const float* __restrict__ Alog,
                                           int d, float& a1) {
    a1 = -__expf(Alog[d*DS + 0]);
    bool fast = true;
#pragma unroll
    for (int s = 0; s < DS; s++) {
        float as = -__expf(Alog[d*DS + s]);
        fast = fast && (fabsf(as - (float)(s+1)*a1) <= 1e-4f*fabsf(as) + 1e-12f);
    }
    return fast;
}

// ---------------- K6a: chunk-local scan (one block per (b,chunk)) ----------
__global__ void __launch_bounds__(768)
k_scan1(const float* __restrict__ Alog) {
    __shared__ float sB[CH*DS];
    int blk = blockIdx.x;
    int chunk = blk & (NC-1), b = blk / NC;
    int d = threadIdx.x;
    int mbase = b*LSEQ + chunk*CH;
    if (d < CH*DS) {
        int t = d >> 4, s = d & 15;
        sB[d] = g_dbc[(size_t)(mbase+t)*DBC_S + DTR + s];
    }
    __syncthreads();

    float a1; bool fast = fast_check(Alog, d, a1);
    float h[DS], P[DS];
#pragma unroll
    for (int s = 0; s < DS; s++) { h[s] = 0.f; P[s] = 1.f; }

    float delta = g_delta[(size_t)mbase*DI + d];
    float u     = g_u   [(size_t)mbase*DI + d];
    for (int t = 0; t < CH; t++) {
        float nd = 0.f, nu = 0.f;
        if (t + 1 < CH) {
            nd = g_delta[(size_t)(mbase+t+1)*DI + d];
            nu = g_u   [(size_t)(mbase+t+1)*DI + d];
        }
        float dbu = delta * u;
        float dA[DS];
        scan_dA(fast, a1, delta, Alog, d, dA);
        const float* Bt = &sB[t*DS];
#pragma unroll
        for (int s = 0; s < DS; s++) {
            h[s] = fmaf(dA[s], h[s], dbu * Bt[s]);
            P[s] *= dA[s];
        }
        delta = nd; u = nu;
    }
    size_t o = (((size_t)(b*NC + chunk))*DI + d)*DS;
#pragma unroll
    for (int s = 0; s < DS; s++) { g_hend[o+s] = h[s]; g_pend[o+s] = P[s]; }
}

// ---------------- K6b: sequential chunk combine ----------------------------
__global__ void k_comb() {
    int g = blockIdx.x*256 + threadIdx.x;   // B*DI*DS threads
    int s = g % DS; int d = (g/DS) % DI; int b = g/(DS*DI);
    float h = 0.f;
#pragma unroll 4
    for (int c = 0; c < NC; c++) {
        size_t o = (((size_t)(b*NC + c))*DI + d)*DS + s;
        g_hin[o] = h;
        h = fmaf(g_pend[o], h, g_hend[o]);
    }
}

// ---------------- K6c: replay + epilogue, writes bf16x2 A' [hi|lo] ---------
__global__ void __launch_bounds__(768)
k_scan2(const float* __restrict__ Alog, const float* __restrict__ Dw,
        __nv_bfloat16* __restrict__ a2) {
    __shared__ float sB[CH*DS];
    __shared__ float sC[CH*DS];
    int blk = blockIdx.x;
    int chunk = blk & (NC-1), b = blk / NC;
    int d = threadIdx.x;
    int mbase = b*LSEQ + chunk*CH;
    if (d < CH*DS) {
        int t = d >> 4, s = d & 15;
        sB[d] = g_dbc[(size_t)(mbase+t)*DBC_S + DTR + s];
        sC[d] = g_dbc[(size_t)(mbase+t)*DBC_S + DTR + DS + s];
    }
    __syncthreads();

    float a1; bool fast = fast_check(Alog, d, a1);
    float Dval = Dw[d];
    float h[DS];
    size_t o = (((size_t)(b*NC + chunk))*DI + d)*DS;
#pragma unroll
    for (int s = 0; s < DS; s++) h[s] = g_hin[o + s];

    float delta = g_delta[(size_t)mbase*DI + d];
    float u     = g_u   [(size_t)mbase*DI + d];
    for (int t = 0; t < CH; t++) {
        int m = mbase + t;
        float nd = 0.f, nu = 0.f;
        if (t + 1 < CH) {
            nd = g_delta[(size_t)(m+1)*DI + d];
            nu = g_u   [(size_t)(m+1)*DI + d];
        }
        float dbu = delta * u;
        float dA[DS];
        scan_dA(fast, a1, delta, Alog, d, dA);
        const float* Bt = &sB[t*DS];
        const float* Ct = &sC[t*DS];
        float y0 = 0.f, y1 = 0.f, y2 = 0.f, y3 = 0.f;
#pragma unroll
        for (int s = 0; s < 4; s++) {
            h[s]    = fmaf(dA[s],    h[s],    dbu*Bt[s]);    y0 = fmaf(h[s],    Ct[s],    y0);
            h[s+4]  = fmaf(dA[s+4],  h[s+4],  dbu*Bt[s+4]);  y1 = fmaf(h[s+4],  Ct[s+4],  y1);
            h[s+8]  = fmaf(dA[s+8],  h[s+8],  dbu*Bt[s+8]);  y2 = fmaf(h[s+8],  Ct[s+8],  y2);
            h[s+12] = fmaf(dA[s+12], h[s+12], dbu*Bt[s+12]); y3 = fmaf(h[s+12], Ct[s+12], y3);
        }
        float y = (y0 + y1) + (y2 + y3);
        float zz = g_xz[(size_t)m*(2*DI) + DI + d];
        float sz = zz / (1.f + __expf(-zz));
        float yo = (y + u*Dval) * sz;
        __nv_bfloat16 hi = __float2bfloat16(yo);
        __nv_bfloat16 lo = __float2bfloat16(yo - __bfloat162float(hi));
        __nv_bfloat16* ap = a2 + (size_t)m * 2 * DI;
        ap[d] = hi; ap[DI + d] = lo;
        delta = nd; u = nu;
    }
}

// ---------------- K9: residual + layernorm2 (sums 2 out_proj partials) -----
__global__ void k_ln2(const float* __restrict__ xt,
                      const float* __restrict__ w,
                      const float* __restrict__ bias) {
    int m = blockIdx.x;
    int tid = threadIdx.x;
    const float* xp = xt + (size_t)m * CDIM;
    float v[3]; float s = 0.f, s2 = 0.f;
#pragma unroll
    for (int i = 0; i < 3; i++) {
        int c = tid + i*128;
        float t = xp[c] + g_mo[(size_t)m*CDIM + c]
                        + g_mo[(size_t)MR*CDIM + (size_t)m*CDIM + c];
        v[i] = t; s += t; s2 += t*t;
    }
    __shared__ float sh1[128], sh2[128];
    sh1[tid] = s; sh2[tid] = s2; __syncthreads();
    for (int o = 64; o > 0; o >>= 1) {
        if (tid < o) { sh1[tid] += sh1[tid+o]; sh2[tid] += sh2[tid+o]; }
        __syncthreads();
    }
    float mu  = sh1[0] * (1.f/CDIM);
    float var = sh2[0] * (1.f/CDIM) - mu*mu;
    float rs  = rsqrtf(var + 1e-5f);
#pragma unroll
    for (int i = 0; i < 3; i++) {
        int c = tid + i*128;
        g_res[(size_t)m*CDIM + c] = (v[i]-mu)*rs*w[c] + bias[c];
    }
}

// ---------------- launch ----------------------------------------------------
extern "C" void kernel_launch(void* const* d_in, const int* in_sizes, int n_in,
                              void* d_out, int out_size) {
    const float* x      = (const float*)d_in[0];
    const float* ln1w   = (const float*)d_in[1];
    const float* ln1b   = (const float*)d_in[2];
    const float* ln2w   = (const float*)d_in[3];
    const float* ln2b   = (const float*)d_in[4];
    const float* inpw   = (const float*)d_in[5];   // (1536, 384)
    const float* convw  = (const float*)d_in[6];   // (768, 1, 4)
    const float* convb  = (const float*)d_in[7];
    const float* xprojw = (const float*)d_in[8];   // (56, 768)
    const float* dtw    = (const float*)d_in[9];   // (768, 24)
    const float* dtb    = (const float*)d_in[10];
    const float* alog   = (const float*)d_in[11];  // (768, 16)
    const float* Dd     = (const float*)d_in[12];
    const float* outpw  = (const float*)d_in[13];  // (384, 768)
    float* out = (float*)d_out;

    float *p_xt, *p_xz, *p_mo, *p_res;
    __nv_bfloat16 *p_a1, *p_w1, *p_a2, *p_w2;
    cudaGetSymbolAddress((void**)&p_xt,  g_xt);
    cudaGetSymbolAddress((void**)&p_xz,  g_xz);
    cudaGetSymbolAddress((void**)&p_mo,  g_mo);
    cudaGetSymbolAddress((void**)&p_res, g_res);
    cudaGetSymbolAddress((void**)&p_a1,  g_a1);
    cudaGetSymbolAddress((void**)&p_w1,  g_w1);
    cudaGetSymbolAddress((void**)&p_a2,  g_a2);
    cudaGetSymbolAddress((void**)&p_w2,  g_w2);

    static const int BG_SMEM = PIPE * STGB;   // 81920 bytes
    cudaFuncSetAttribute(k_bgemm, cudaFuncAttributeMaxDynamicSharedMemorySize, BG_SMEM);

    // x (B,C,L) -> g_xt (B,L,C)
    k_tr    <<<dim3(LSEQ/32, CDIM/32, BATCH), dim3(32,8)>>>(x, p_xt, CDIM, LSEQ);
    k_ln1   <<<MR, 128>>>(p_xt, ln1w, ln1b, p_a1);
    // in_proj: bf16x2 -> mma.sync GEMM (K2 = 768)
    k_cvt   <<<(2*DI*CDIM)/256, 256>>>(inpw, p_w1, CDIM);
    k_bgemm <<<dim3(2*DI/128, MR/128, 1), 256, BG_SMEM>>>(p_a1, p_w1, p_xz,
                                                          2*DI, 2*CDIM, 2*CDIM, 0);
    k_conv  <<<(MR*DI)/256, 256>>>(convw, convb);
    k_xproj <<<dim3(MR/64, XSPL), 256>>>(xprojw);
    k_dbcred<<<(MR*DBC_S)/256, 256>>>();
    k_dtproj<<<MR/16, 256>>>(dtw, dtb);
    k_scan1 <<<BATCH*NC, 768>>>(alog);
    k_comb  <<<(BATCH*DI*DS)/256, 256>>>();
    k_scan2 <<<BATCH*NC, 768>>>(alog, Dd, p_a2);
    // out_proj: bf16x2 -> mma.sync GEMM, K-split 2 (K2 = 1536, Kl = 768)
    k_cvt   <<<(CDIM*DI)/256, 256>>>(outpw, p_w2, DI);
    k_bgemm <<<dim3(CDIM/128, MR/128, 2), 256, BG_SMEM>>>(p_a2, p_w2, p_mo,
                                                          CDIM, DI, 2*DI, MR*CDIM);
    k_ln2   <<<MR, 128>>>(p_xt, ln2w, ln2b);
    // g_res (B,L,C) -> out (B,C,L)
    k_tr    <<<dim3(CDIM/32, LSEQ/32, BATCH), dim3(32,8)>>>(p_res, out, LSEQ, CDIM);
}

// round 14
// speedup vs baseline: 2.0556x; 1.0001x over previous
#include <cuda_runtime.h>
#include <cuda_bf16.h>
#include <math.h>
#include <stdint.h>

#define BATCH   2
#define LSEQ    2048
#define CDIM    384
#define DI      768
#define DS      16
#define DTR     24
#define MR      (BATCH*LSEQ)     /* 4096 rows */
#define NC      64               /* scan chunks */
#define CH      (LSEQ/NC)        /* 32 steps per chunk */
#define DBC_S   64               /* padded stride for dbc rows (56 used) */
#define XSPL    8                /* x_proj K-split */

// ---------------- scratch (static device globals; no allocation) ----------
__device__ float g_xz   [MR*2*DI];       // in_proj output (u | z)
__device__ float g_u    [MR*DI];         // conv+silu output
__device__ float g_dbcp [XSPL*MR*DBC_S]; // x_proj K-split partials
__device__ float g_dbc  [MR*DBC_S];      // x_proj output (dt|B|C), padded
__device__ float g_delta[MR*DI];         // softplus(dt_proj)
__device__ float g_mo   [2*MR*CDIM];     // out_proj K-split partials
__device__ float g_hend [BATCH*NC*DI*DS];
__device__ float g_pend [BATCH*NC*DI*DS];
__device__ float g_hin  [BATCH*NC*DI*DS];
// bf16x2 split operands: A' = [hi | lo], W' = [hi | hi]
__device__ __align__(16) __nv_bfloat16 g_a1[MR*2*CDIM];    // in_proj A'  [4096,768]
__device__ __align__(16) __nv_bfloat16 g_w1[2*DI*2*CDIM];  // in_proj W'  [1536,768]
__device__ __align__(16) __nv_bfloat16 g_a2[MR*2*DI];      // out_proj A' [4096,1536]
__device__ __align__(16) __nv_bfloat16 g_w2[CDIM*2*DI];    // out_proj W' [384,1536]

// ---------------- helpers ---------------------------------------------------
__device__ __forceinline__ uint32_t smem_u32(const void* p) {
    uint32_t a;
    asm("{ .reg .u64 t; cvta.to.shared.u64 t, %1; cvt.u32.u64 %0, t; }"
        : "=r"(a) : "l"(p));
    return a;
}
#define LDSM4(r0, r1, r2, r3, a) \
    asm volatile("ldmatrix.sync.aligned.m8n8.x4.shared.b16 {%0,%1,%2,%3}, [%4];" \
                 : "=r"(r0), "=r"(r1), "=r"(r2), "=r"(r3) : "r"(a))
#define MMA16816(c, a, b) \
    asm volatile("mma.sync.aligned.m16n8k16.row.col.f32.bf16.bf16.f32 " \
                 "{%0,%1,%2,%3}, {%4,%5,%6,%7}, {%8,%9}, {%0,%1,%2,%3};" \
                 : "+f"((c)[0]), "+f"((c)[1]), "+f"((c)[2]), "+f"((c)[3]) \
                 : "r"((a)[0]), "r"((a)[1]), "r"((a)[2]), "r"((a)[3]), \
                   "r"((b)[0]), "r"((b)[1]))
#define CP_ASYNC16(dst, src) \
    asm volatile("cp.async.cg.shared.global [%0], [%1], 16;" :: "r"(dst), "l"(src))
#define CP_COMMIT() asm volatile("cp.async.commit_group;" ::: "memory")
#define CP_WAIT2()  asm volatile("cp.async.wait_group 2;" ::: "memory")
#define CP_WAIT1()  asm volatile("cp.async.wait_group 1;" ::: "memory")
#define CP_WAIT0()  asm volatile("cp.async.wait_group 0;" ::: "memory")

// ---------------- bf16x2 weight conversion ([hi|hi]) -----------------------
__global__ void k_cvt(const float* __restrict__ src, __nv_bfloat16* __restrict__ dst,
                      int K) {
    size_t i = (size_t)blockIdx.x * 256 + threadIdx.x;
    int r = (int)(i / K), k = (int)(i % K);
    float a = src[i];
    __nv_bfloat16 hi = __float2bfloat16(a);
    size_t base = (size_t)r * 2 * K;
    dst[base + k] = hi; dst[base + K + k] = hi;
}

// ---------------- bf16 mma.sync GEMM, cp.async 4-stage pipeline ------------
#define KCH   32
#define SROW  40            /* padded SMEM row, bf16 elems (80B, 16B-mult) */
#define SSTG  (128*SROW)    /* elems per operand per stage */
#define PIPE  4
#define STGB  (2*SSTG*2)    /* bytes per stage block (A then W) */

__global__ void __launch_bounds__(256, 2)
k_bgemm(const __nv_bfloat16* __restrict__ A, const __nv_bfloat16* __restrict__ W,
        float* __restrict__ C, int N, int Kl, int lda, int cstride) {
    extern __shared__ __align__(16) __nv_bfloat16 dsm[];
    uint32_t dynB = smem_u32(dsm);

    int tid = threadIdx.x, lane = tid & 31, wid = tid >> 5;
    int warp_m = wid & 3, warp_n = wid >> 2;          // 4 x 2 warps
    int m0 = blockIdx.y * 128, n0 = blockIdx.x * 128;
    int z = blockIdx.z;
    A += (size_t)z * Kl;
    W += (size_t)z * Kl;
    C += (size_t)z * cstride;

    int c0r = tid >> 2,         c0g = tid & 3;
    int c1r = (tid + 256) >> 2, c1g = c0g;
    const __nv_bfloat16* A0 = A + (size_t)(m0 + c0r) * lda + c0g * 8;
    const __nv_bfloat16* A1 = A + (size_t)(m0 + c1r) * lda + c1g * 8;
    const __nv_bfloat16* W0 = W + (size_t)(n0 + c0r) * lda + c0g * 8;
    const __nv_bfloat16* W1 = W + (size_t)(n0 + c1r) * lda + c1g * 8;
    uint32_t sd0 = (uint32_t)(c0r * SROW * 2 + c0g * 16);
    uint32_t sd1 = (uint32_t)(c1r * SROW * 2 + c1g * 16);

    uint32_t aOff = (uint32_t)((warp_m*32 + (lane & 15)) * SROW + ((lane >> 4) & 1) * 8) * 2;
    uint32_t bOff = (uint32_t)((warp_n*64 + (lane & 7) + ((lane >> 4) & 1) * 8) * SROW
                               + ((lane >> 3) & 1) * 8) * 2;

    float acc[2][8][4];
#pragma unroll
    for (int i = 0; i < 2; i++)
#pragma unroll
        for (int j = 0; j < 8; j++)
#pragma unroll
            for (int q = 0; q < 4; q++) acc[i][j][q] = 0.f;

    int NKC = Kl / KCH;

#define LOAD_STAGE(st, kc) do {                                             \
    uint32_t sb = dynB + (uint32_t)(st) * STGB;                             \
    CP_ASYNC16(sb + sd0,            A0 + (size_t)(kc) * KCH);               \
    CP_ASYNC16(sb + sd1,            A1 + (size_t)(kc) * KCH);               \
    CP_ASYNC16(sb + 2*SSTG + sd0,   W0 + (size_t)(kc) * KCH);               \
    CP_ASYNC16(sb + 2*SSTG + sd1,   W1 + (size_t)(kc) * KCH);               \
} while (0)

    LOAD_STAGE(0, 0); CP_COMMIT();
    LOAD_STAGE(1, 1); CP_COMMIT();
    LOAD_STAGE(2, 2); CP_COMMIT();

    int st = 0;
    for (int kc = 0; kc < NKC; kc++) {
        if (kc < NKC - 2)      { CP_WAIT2(); }
        else if (kc == NKC - 2){ CP_WAIT1(); }
        else                   { CP_WAIT0(); }
        __syncthreads();
        if (kc + 3 < NKC) {
            int nst = st + 3; if (nst >= PIPE) nst -= PIPE;
            LOAD_STAGE(nst, kc + 3); CP_COMMIT();
        }
        uint32_t aS = dynB + (uint32_t)st * STGB + aOff;
        uint32_t bS = dynB + (uint32_t)st * STGB + 2*SSTG + bOff;
#pragma unroll
        for (int ks = 0; ks < 2; ks++) {
            uint32_t af[2][4];
#pragma unroll
            for (int mi = 0; mi < 2; mi++)
                LDSM4(af[mi][0], af[mi][1], af[mi][2], af[mi][3],
                      aS + (uint32_t)(mi*16*SROW + ks*16) * 2);
            uint32_t bf[8][2];
#pragma unroll
            for (int p = 0; p < 4; p++) {
                uint32_t r0, r1, r2, r3;
                LDSM4(r0, r1, r2, r3, bS + (uint32_t)(p*16*SROW + ks*16) * 2);
                bf[2*p][0] = r0;   bf[2*p][1] = r1;
                bf[2*p+1][0] = r2; bf[2*p+1][1] = r3;
            }
#pragma unroll
            for (int mi = 0; mi < 2; mi++)
#pragma unroll
                for (int nj = 0; nj < 8; nj++)
                    MMA16816(acc[mi][nj], af[mi], bf[nj]);
        }
        if (++st >= PIPE) st -= PIPE;
    }

    int rbase = m0 + warp_m*32 + (lane >> 2);
    int cbase = n0 + warp_n*64 + (lane & 3)*2;
#pragma unroll
    for (int mi = 0; mi < 2; mi++) {
#pragma unroll
        for (int nj = 0; nj < 8; nj++) {
            float* cp0 = C + (size_t)(rbase + mi*16) * N + cbase + nj*8;
            float* cp1 = cp0 + 8*N;
            *(float2*)cp0 = make_float2(acc[mi][nj][0], acc[mi][nj][1]);
            *(float2*)cp1 = make_float2(acc[mi][nj][2], acc[mi][nj][3]);
        }
    }
}

// ---------------- K1: fused transpose + layernorm1 -> bf16x2 A' [hi|lo] ----
__global__ void __launch_bounds__(256)
k_ln1t(const float* __restrict__ x, const float* __restrict__ w,
       const float* __restrict__ bias, __nv_bfloat16* __restrict__ a1) {
    __shared__ float sx[16][385];
    __shared__ float smu[16], srs[16];
    int m0 = blockIdx.x * 16;
    int b = m0 / LSEQ, l0 = m0 % LSEQ;
    int tid = threadIdx.x;
    const float* xb = x + (size_t)b*CDIM*LSEQ + l0;
    for (int idx = tid; idx < 16*CDIM; idx += 256) {
        int i = idx & 15, c = idx >> 4;
        sx[i][c] = xb[(size_t)c*LSEQ + i];
    }
    __syncthreads();
    int wid = tid >> 5, lane = tid & 31;
    for (int r = wid; r < 16; r += 8) {
        float s = 0.f, s2 = 0.f;
        for (int c = lane; c < CDIM; c += 32) { float t = sx[r][c]; s += t; s2 += t*t; }
#pragma unroll
        for (int o = 16; o; o >>= 1) {
            s  += __shfl_xor_sync(0xFFFFFFFFu, s,  o);
            s2 += __shfl_xor_sync(0xFFFFFFFFu, s2, o);
        }
        if (lane == 0) {
            float mu = s * (1.f/CDIM);
            float var = s2 * (1.f/CDIM) - mu*mu;
            smu[r] = mu; srs[r] = rsqrtf(var + 1e-5f);
        }
    }
    __syncthreads();
    for (int idx = tid; idx < 16*CDIM; idx += 256) {
        int r = idx / CDIM, c = idx % CDIM;
        float t = (sx[r][c] - smu[r]) * srs[r] * w[c] + bias[c];
        __nv_bfloat16 hi = __float2bfloat16(t);
        __nv_bfloat16 lo = __float2bfloat16(t - __bfloat162float(hi));
        __nv_bfloat16* ap = a1 + (size_t)(m0 + r) * 2 * CDIM;
        ap[c] = hi; ap[CDIM + c] = lo;
    }
}

// ---------------- K4: fused conv+silu + x_proj partial ---------------------
// Block: 64-row m-tile (bx), K-slice z (96 cols). Computes u from g_xz with a
// 3-row halo, applies conv+silu in SMEM, writes g_u, accumulates dbc partials.
// NOTE: all float4-accessed shared arrays are 16B-aligned (round-12 bug fix).
__global__ void __launch_bounds__(256)
k_cxproj(const float* __restrict__ W, const float* __restrict__ cw,
         const float* __restrict__ cb) {
    __shared__ __align__(16) float us[32][68];   // [k][m]  (float4 reads)
    __shared__ __align__(16) float sxz[67][33];
    __shared__ __align__(16) float ws[56][33];   // [n][k]
    __shared__ __align__(16) float scw[32][4];
    __shared__ float scb[32];
    int tid = threadIdx.x;
    int m0 = blockIdx.x * 64;
    int z  = blockIdx.y;
    int kb0 = z * (DI/XSPL);       // 96
    int n  = tid & 63, mg = tid >> 6;
    int nn = (n < 56) ? n : 55;
    bool lzero = (m0 % LSEQ) == 0;
    float acc[16];
#pragma unroll
    for (int i = 0; i < 16; i++) acc[i] = 0.f;

    for (int kb = 0; kb < 3; kb++) {
        int k0 = kb0 + kb*32;
        __syncthreads();
        // xz tile with halo: rows 0..66 <-> global m0-3+r, cols k0..k0+31
        for (int v = tid; v < 67*8; v += 256) {
            int r = v >> 3, q = v & 7;
            float4 t;
            if (r < 3 && lzero) t = make_float4(0.f, 0.f, 0.f, 0.f);
            else t = *(const float4*)(g_xz + (size_t)(m0 - 3 + r)*(2*DI) + k0 + q*4);
            sxz[r][q*4+0] = t.x; sxz[r][q*4+1] = t.y;
            sxz[r][q*4+2] = t.z; sxz[r][q*4+3] = t.w;
        }
        if (tid < 32) {
            scb[tid] = cb[k0 + tid];
            float4 t = *(const float4*)(cw + (size_t)(k0 + tid)*4);
            scw[tid][0] = t.x; scw[tid][1] = t.y; scw[tid][2] = t.z; scw[tid][3] = t.w;
        }
        for (int v = tid; v < 448; v += 256) {
            int nr = v >> 3, kq = v & 7;
            float4 t = *(const float4*)(W + (size_t)nr*DI + k0 + kq*4);
            ws[nr][kq*4+0] = t.x; ws[nr][kq*4+1] = t.y;
            ws[nr][kq*4+2] = t.z; ws[nr][kq*4+3] = t.w;
        }
        __syncthreads();
        // conv + silu: thread handles (m = tid&63, 8 k's)
        {
            int m = tid & 63, kq = tid >> 6;
            float vals[8];
#pragma unroll
            for (int e = 0; e < 8; e++) {
                int k = kq*8 + e;
                float a = scb[k];
#pragma unroll
                for (int j = 0; j < 4; j++)
                    a = fmaf(scw[k][j], sxz[m + j][k], a);
                float sg = 1.f / (1.f + __expf(-a));
                float uv = a * sg;
                vals[e] = uv;
                us[k][m] = uv;
            }
            float* up = g_u + (size_t)(m0 + m)*DI + k0 + kq*8;
            *(float4*)up       = make_float4(vals[0], vals[1], vals[2], vals[3]);
            *(float4*)(up + 4) = make_float4(vals[4], vals[5], vals[6], vals[7]);
        }
        __syncthreads();
#pragma unroll 4
        for (int kk = 0; kk < 32; kk++) {
            float wv = ws[nn][kk];
            float4 u0 = *(const float4*)&us[kk][mg*16+0];
            float4 u1 = *(const float4*)&us[kk][mg*16+4];
            float4 u2 = *(const float4*)&us[kk][mg*16+8];
            float4 u3 = *(const float4*)&us[kk][mg*16+12];
            acc[0]  = fmaf(u0.x, wv, acc[0]);  acc[1]  = fmaf(u0.y, wv, acc[1]);
            acc[2]  = fmaf(u0.z, wv, acc[2]);  acc[3]  = fmaf(u0.w, wv, acc[3]);
            acc[4]  = fmaf(u1.x, wv, acc[4]);  acc[5]  = fmaf(u1.y, wv, acc[5]);
            acc[6]  = fmaf(u1.z, wv, acc[6]);  acc[7]  = fmaf(u1.w, wv, acc[7]);
            acc[8]  = fmaf(u2.x, wv, acc[8]);  acc[9]  = fmaf(u2.y, wv, acc[9]);
            acc[10] = fmaf(u2.z, wv, acc[10]); acc[11] = fmaf(u2.w, wv, acc[11]);
            acc[12] = fmaf(u3.x, wv, acc[12]); acc[13] = fmaf(u3.y, wv, acc[13]);
            acc[14] = fmaf(u3.z, wv, acc[14]); acc[15] = fmaf(u3.w, wv, acc[15]);
        }
    }
    if (n < 56) {
#pragma unroll
        for (int i = 0; i < 16; i++)
            g_dbcp[((size_t)z*MR + m0 + mg*16 + i)*DBC_S + n] = acc[i];
    }
}

// ---------------- K4b: reduce the K-split partials -------------------------
__global__ void k_dbcred() {
    size_t i = (size_t)blockIdx.x*256 + threadIdx.x;    // < MR*DBC_S
    float s = 0.f;
#pragma unroll
    for (int z = 0; z < XSPL; z++) s += g_dbcp[(size_t)z*MR*DBC_S + i];
    g_dbc[i] = s;
}

// ---------------- K5: dt_proj + softplus -> delta --------------------------
__global__ void k_dtproj(const float* __restrict__ W, const float* __restrict__ bias) {
    __shared__ float sdt[16][24];
    int tid = threadIdx.x;
    int m0 = blockIdx.x * 16;
    for (int idx = tid; idx < 16*24; idx += 256) {
        int mi = idx / 24, r = idx % 24;
        sdt[mi][r] = g_dbc[(size_t)(m0+mi)*DBC_S + r];
    }
    __syncthreads();
    for (int d = tid; d < DI; d += 256) {
        float wr[24];
#pragma unroll
        for (int r = 0; r < 24; r++) wr[r] = W[d*24 + r];
        float bz = bias[d];
        for (int mi = 0; mi < 16; mi++) {
            float a = bz;
#pragma unroll
            for (int r = 0; r < 24; r++) a = fmaf(sdt[mi][r], wr[r], a);
            float sp = (a > 20.f) ? a : log1pf(expf(a));
            g_delta[(size_t)(m0+mi)*DI + d] = sp;
        }
    }
}

// ---------------- scan helpers ---------------------------------------------
__device__ __forceinline__ void scan_dA(bool fast, float a1, float delta,
                                        const float* __restrict__ Alog, int d,
                                        float dA[DS]) {
    if (fast) {
        float p = __expf(delta * a1);      // dA[s] = p^(s+1)
        dA[0] = p;
#pragma unroll
        for (int s = 1; s < DS; s++) dA[s] = dA[s-1] * p;
    } else {
#pragma unroll
        for (int s = 0; s < DS; s++)
            dA[s] = __expf(delta * (-__expf(Alog[d*DS + s])));
    }
}

__device__ __forceinline__ bool fast_check(const float* __restrict__ Alog,
                                           int d, float& a1) {
    a1 = -__expf(Alog[d*DS + 0]);
    bool fast = true;
#pragma unroll
    for (int s = 0; s < DS; s++) {
        float as = -__expf(Alog[d*DS + s]);
        fast = fast && (fabsf(as - (float)(s+1)*a1) <= 1e-4f*fabsf(as) + 1e-12f);
    }
    return fast;
}

// ---------------- K6a: chunk-local scan (one block per (b,chunk)) ----------
__global__ void __launch_bounds__(768)
k_scan1(const float* __restrict__ Alog) {
    __shared__ float sB[CH*DS];
    int blk = blockIdx.x;
    int chunk = blk & (NC-1), b = blk / NC;
    int d = threadIdx.x;
    int mbase = b*LSEQ + chunk*CH;
    if (d < CH*DS) {
        int t = d >> 4, s = d & 15;
        sB[d] = g_dbc[(size_t)(mbase+t)*DBC_S + DTR + s];
    }
    __syncthreads();

    float a1; bool fast = fast_check(Alog, d, a1);
    float h[DS], P[DS];
#pragma unroll
    for (int s = 0; s < DS; s++) { h[s] = 0.f; P[s] = 1.f; }

    float delta = g_delta[(size_t)mbase*DI + d];
    float u     = g_u   [(size_t)mbase*DI + d];
    for (int t = 0; t < CH; t++) {
        float nd = 0.f, nu = 0.f;
        if (t + 1 < CH) {
            nd = g_delta[(size_t)(mbase+t+1)*DI + d];
            nu = g_u   [(size_t)(mbase+t+1)*DI + d];
        }
        float dbu = delta * u;
        float dA[DS];
        scan_dA(fast, a1, delta, Alog, d, dA);
        const float* Bt = &sB[t*DS];
#pragma unroll
        for (int s = 0; s < DS; s++) {
            h[s] = fmaf(dA[s], h[s], dbu * Bt[s]);
            P[s] *= dA[s];
        }
        delta = nd; u = nu;
    }
    size_t o = (((size_t)(b*NC + chunk))*DI + d)*DS;
#pragma unroll
    for (int s = 0; s < DS; s++) { g_hend[o+s] = h[s]; g_pend[o+s] = P[s]; }
}

// ---------------- K6b: sequential chunk combine ----------------------------
__global__ void k_comb() {
    int g = blockIdx.x*256 + threadIdx.x;   // B*DI*DS threads
    int s = g % DS; int d = (g/DS) % DI; int b = g/(DS*DI);
    float h = 0.f;
#pragma unroll 4
    for (int c = 0; c < NC; c++) {
        size_t o = (((size_t)(b*NC + c))*DI + d)*DS + s;
        g_hin[o] = h;
        h = fmaf(g_pend[o], h, g_hend[o]);
    }
}

// ---------------- K6c: replay + epilogue, writes bf16x2 A' [hi|lo] ---------
__global__ void __launch_bounds__(768)
k_scan2(const float* __restrict__ Alog, const float* __restrict__ Dw,
        __nv_bfloat16* __restrict__ a2) {
    __shared__ float sB[CH*DS];
    __shared__ float sC[CH*DS];
    int blk = blockIdx.x;
    int chunk = blk & (NC-1), b = blk / NC;
    int d = threadIdx.x;
    int mbase = b*LSEQ + chunk*CH;
    if (d < CH*DS) {
        int t = d >> 4, s = d & 15;
        sB[d] = g_dbc[(size_t)(mbase+t)*DBC_S + DTR + s];
        sC[d] = g_dbc[(size_t)(mbase+t)*DBC_S + DTR + DS + s];
    }
    __syncthreads();

    float a1; bool fast = fast_check(Alog, d, a1);
    float Dval = Dw[d];
    float h[DS];
    size_t o = (((size_t)(b*NC + chunk))*DI + d)*DS;
#pragma unroll
    for (int s = 0; s < DS; s++) h[s] = g_hin[o + s];

    float delta = g_delta[(size_t)mbase*DI + d];
    float u     = g_u   [(size_t)mbase*DI + d];
    for (int t = 0; t < CH; t++) {
        int m = mbase + t;
        float nd = 0.f, nu = 0.f;
        if (t + 1 < CH) {
            nd = g_delta[(size_t)(m+1)*DI + d];
            nu = g_u   [(size_t)(m+1)*DI + d];
        }
        float dbu = delta * u;
        float dA[DS];
        scan_dA(fast, a1, delta, Alog, d, dA);
        const float* Bt = &sB[t*DS];
        const float* Ct = &sC[t*DS];
        float y0 = 0.f, y1 = 0.f, y2 = 0.f, y3 = 0.f;
#pragma unroll
        for (int s = 0; s < 4; s++) {
            h[s]    = fmaf(dA[s],    h[s],    dbu*Bt[s]);    y0 = fmaf(h[s],    Ct[s],    y0);
            h[s+4]  = fmaf(dA[s+4],  h[s+4],  dbu*Bt[s+4]);  y1 = fmaf(h[s+4],  Ct[s+4],  y1);
            h[s+8]  = fmaf(dA[s+8],  h[s+8],  dbu*Bt[s+8]);  y2 = fmaf(h[s+8],  Ct[s+8],  y2);
            h[s+12] = fmaf(dA[s+12], h[s+12], dbu*Bt[s+12]); y3 = fmaf(h[s+12], Ct[s+12], y3);
        }
        float y = (y0 + y1) + (y2 + y3);
        float zz = g_xz[(size_t)m*(2*DI) + DI + d];
        float sz = zz / (1.f + __expf(-zz));
        float yo = (y + u*Dval) * sz;
        __nv_bfloat16 hi = __float2bfloat16(yo);
        __nv_bfloat16 lo = __float2bfloat16(yo - __bfloat162float(hi));
        __nv_bfloat16* ap = a2 + (size_t)m * 2 * DI;
        ap[d] = hi; ap[DI + d] = lo;
        delta = nd; u = nu;
    }
}

// ---------------- K9: fused residual + layernorm2 + output transpose -------
__global__ void __launch_bounds__(256)
k_ln2t(const float* __restrict__ x, const float* __restrict__ w,
       const float* __restrict__ bias, float* __restrict__ out) {
    __shared__ float sx[16][385];
    __shared__ float smu[16], srs[16];
    int m0 = blockIdx.x * 16;
    int b = m0 / LSEQ, l0 = m0 % LSEQ;
    int tid = threadIdx.x;
    const float* xb = x + (size_t)b*CDIM*LSEQ + l0;
    for (int idx = tid; idx < 16*CDIM; idx += 256) {
        int i = idx & 15, c = idx >> 4;
        sx[i][c] = xb[(size_t)c*LSEQ + i];
    }
    __syncthreads();
    for (int idx = tid; idx < 16*CDIM; idx += 256) {
        int r = idx / CDIM, c = idx % CDIM;
        int m = m0 + r;
        sx[r][c] += g_mo[(size_t)m*CDIM + c]
                  + g_mo[(size_t)MR*CDIM + (size_t)m*CDIM + c];
    }
    __syncthreads();
    int wid = tid >> 5, lane = tid & 31;
    for (int r = wid; r < 16; r += 8) {
        float s = 0.f, s2 = 0.f;
        for (int c = lane; c < CDIM; c += 32) { float t = sx[r][c]; s += t; s2 += t*t; }
#pragma unroll
        for (int o = 16; o; o >>= 1) {
            s  += __shfl_xor_sync(0xFFFFFFFFu, s,  o);
            s2 += __shfl_xor_sync(0xFFFFFFFFu, s2, o);
        }
        if (lane == 0) {
            float mu = s * (1.f/CDIM);
            float var = s2 * (1.f/CDIM) - mu*mu;
            smu[r] = mu; srs[r] = rsqrtf(var + 1e-5f);
        }
    }
    __syncthreads();
    float* ob = out + (size_t)b*CDIM*LSEQ + l0;
    for (int idx = tid; idx < 16*CDIM; idx += 256) {
        int i = idx & 15, c = idx >> 4;
        float t = (sx[i][c] - smu[i]) * srs[i] * w[c] + bias[c];
        ob[(size_t)c*LSEQ + i] = t;
    }
}

// ---------------- launch ----------------------------------------------------
extern "C" void kernel_launch(void* const* d_in, const int* in_sizes, int n_in,
                              void* d_out, int out_size) {
    const float* x      = (const float*)d_in[0];
    const float* ln1w   = (const float*)d_in[1];
    const float* ln1b   = (const float*)d_in[2];
    const float* ln2w   = (const float*)d_in[3];
    const float* ln2b   = (const float*)d_in[4];
    const float* inpw   = (const float*)d_in[5];   // (1536, 384)
    const float* convw  = (const float*)d_in[6];   // (768, 1, 4)
    const float* convb  = (const float*)d_in[7];
    const float* xprojw = (const float*)d_in[8];   // (56, 768)
    const float* dtw    = (const float*)d_in[9];   // (768, 24)
    const float* dtb    = (const float*)d_in[10];
    const float* alog   = (const float*)d_in[11];  // (768, 16)
    const float* Dd     = (const float*)d_in[12];
    const float* outpw  = (const float*)d_in[13];  // (384, 768)
    float* out = (float*)d_out;

    float *p_xz, *p_mo;
    __nv_bfloat16 *p_a1, *p_w1, *p_a2, *p_w2;
    cudaGetSymbolAddress((void**)&p_xz,  g_xz);
    cudaGetSymbolAddress((void**)&p_mo,  g_mo);
    cudaGetSymbolAddress((void**)&p_a1,  g_a1);
    cudaGetSymbolAddress((void**)&p_w1,  g_w1);
    cudaGetSymbolAddress((void**)&p_a2,  g_a2);
    cudaGetSymbolAddress((void**)&p_w2,  g_w2);

    static const int BG_SMEM = PIPE * STGB;   // 81920 bytes
    cudaFuncSetAttribute(k_bgemm, cudaFuncAttributeMaxDynamicSharedMemorySize, BG_SMEM);

    // weight conversions (independent of activations)
    k_cvt    <<<(2*DI*CDIM)/256, 256>>>(inpw, p_w1, CDIM);
    k_cvt    <<<(CDIM*DI)/256, 256>>>(outpw, p_w2, DI);
    // fused transpose+LN1 -> bf16x2 A'
    k_ln1t   <<<MR/16, 256>>>(x, ln1w, ln1b, p_a1);
    // in_proj GEMM (K2 = 768)
    k_bgemm  <<<dim3(2*DI/128, MR/128, 1), 256, BG_SMEM>>>(p_a1, p_w1, p_xz,
                                                           2*DI, 2*CDIM, 2*CDIM, 0);
    // fused conv+silu + x_proj
    k_cxproj <<<dim3(MR/64, XSPL), 256>>>(xprojw, convw, convb);
    k_dbcred <<<(MR*DBC_S)/256, 256>>>();
    k_dtproj <<<MR/16, 256>>>(dtw, dtb);
    k_scan1  <<<BATCH*NC, 768>>>(alog);
    k_comb   <<<(BATCH*DI*DS)/256, 256>>>();
    k_scan2  <<<BATCH*NC, 768>>>(alog, Dd, p_a2);
    // out_proj GEMM, K-split 2 (K2 = 1536, Kl = 768)
    k_bgemm  <<<dim3(CDIM/128, MR/128, 2), 256, BG_SMEM>>>(p_a2, p_w2, p_mo,
                                                           CDIM, DI, 2*DI, MR*CDIM);
    // fused residual+LN2+transpose-out
    k_ln2t   <<<MR/16, 256>>>(x, ln2w, ln2b, out);
}